// round 12
// baseline (speedup 1.0000x reference)
#include <cuda_runtime.h>
#include <cuda_bf16.h>
#include <stdint.h>
#include <math.h>

#define NN 16384
#define DIN 128
#define DX 256
#define DOUT 128
#define BG 32
#define NPER 512
#define KCL 64
#define ACOLS 2048
#define EMAX 262144
#define ADJ_OFF (2048*2048)

// ================= helpers =================
__device__ __forceinline__ uint32_t smem_to_u32(const void* p) {
    uint32_t a;
    asm("{ .reg .u64 t; cvta.to.shared.u64 t, %1; cvt.u32.u64 %0, t; }"
        : "=r"(a) : "l"(p));
    return a;
}
#define SMEM_SWIZZLE_128B(o) ((o) ^ (((o) >> 3) & 0x70))

__device__ __forceinline__ void ldsm4(uint32_t* r, uint32_t addr) {
    asm volatile("ldmatrix.sync.aligned.m8n8.x4.shared.b16 {%0,%1,%2,%3}, [%4];"
                 : "=r"(r[0]), "=r"(r[1]), "=r"(r[2]), "=r"(r[3]) : "r"(addr));
}
__device__ __forceinline__ void mma_bf16(float* d, const uint32_t* a,
                                         const uint32_t* b) {
    asm volatile(
        "mma.sync.aligned.m16n8k16.row.col.f32.bf16.bf16.f32 "
        "{%0,%1,%2,%3}, {%4,%5,%6,%7}, {%8,%9}, {%0,%1,%2,%3};"
        : "+f"(d[0]), "+f"(d[1]), "+f"(d[2]), "+f"(d[3])
        : "r"(a[0]), "r"(a[1]), "r"(a[2]), "r"(a[3]), "r"(b[0]), "r"(b[1]));
}
__device__ __forceinline__ void cp16(uint32_t saddr, const void* g) {
    asm volatile("cp.async.cg.shared.global [%0], [%1], 16;"
                 :: "r"(saddr), "l"(g));
}
#define CP_COMMIT() asm volatile("cp.async.commit_group;" ::: "memory")
#define CP_WAIT(N)  asm volatile("cp.async.wait_group %0;" :: "n"(N) : "memory")

// ---------------- f32x2 packed-math helpers ----------------
__device__ __forceinline__ unsigned long long pk2(float lo, float hi) {
    unsigned long long r;
    asm("mov.b64 %0, {%1, %2};" : "=l"(r) : "f"(lo), "f"(hi));
    return r;
}
__device__ __forceinline__ void fma2(unsigned long long& d, unsigned long long a,
                                     unsigned long long b) {
    asm("fma.rn.f32x2 %0, %1, %2, %0;" : "+l"(d) : "l"(a), "l"(b));
}
__device__ __forceinline__ float2 up2(unsigned long long v) {
    float lo, hi;
    asm("mov.b64 {%0, %1}, %2;" : "=f"(lo), "=f"(hi) : "l"(v));
    return make_float2(lo, hi);
}

// ---------------- device scratch ----------------
__device__ int   g_off[NN + 1];
__device__ int   g_csr[EMAX];
__device__ __nv_bfloat16 g_Xh[NN * DX];   // bf16 hi of [h | h_neigh]
__device__ __nv_bfloat16 g_Xl[NN * DX];   // bf16 lo
__device__ __nv_bfloat16 g_WTh[384 * DX];     // WT[n][k] hi ([0:128)=Wf^T, [128:384)=M)
__device__ __nv_bfloat16 g_WTl[384 * DX];     // WT[n][k] lo
__device__ __nv_bfloat16 g_WpTh[ACOLS * DX];  // WpT[c][k] hi
__device__ __nv_bfloat16 g_WpTl[ACOLS * DX];  // WpT[c][k] lo
__device__ float g_C[NN * 128];           // feat pre-activation
__device__ float g_q[NN];                 // x^T M x
__device__ float g_feat[NN * DOUT];
__device__ float g_rnp[NN];
__device__ float g_s[NN * KCL];
__device__ float g_u[DX];
__device__ float g_cb;

// ================== k_setup: all independent preprocessing ==================
// blocks [0,32): per-graph CSR
// blocks [32,544): WpT transpose + bf16 split (512 tiles 32x32)
// blocks [544,801): u = Wp@bp reductions, cb = ||bp||^2 (257)
// blocks [801,833): Wf transpose-split -> WT[0:128) (32 tiles)
// blocks [833,849): zero g_q (16 blocks)
__global__ void __launch_bounds__(256, 1) k_setup(
    const float* __restrict__ Wf, const float* __restrict__ Wp,
    const float* __restrict__ bp, const int* __restrict__ src,
    const int* __restrict__ dst, int E) {
    __shared__ int cnt[NPER];
    __shared__ int part[256];
    __shared__ float t[32][33];
    int bid = blockIdx.x;
    int tid = threadIdx.x;

    if (bid < 32) {
        int g = bid;
        int EPG = E / BG;
        int e0 = g * EPG;
        int nbase = g * NPER;
#pragma unroll
        for (int i = tid; i < NPER; i += 256) cnt[i] = 0;
        __syncthreads();
        for (int e = e0 + tid; e < e0 + EPG; e += 256)
            atomicAdd(&cnt[dst[e] - nbase], 1);
        __syncthreads();
        int v0 = cnt[tid * 2], v1 = cnt[tid * 2 + 1];
        part[tid] = v0 + v1;
        __syncthreads();
        for (int off = 1; off < 256; off <<= 1) {
            int v = 0;
            if (tid >= off) v = part[tid - off];
            __syncthreads();
            if (tid >= off) part[tid] += v;
            __syncthreads();
        }
        int excl = (tid == 0) ? 0 : part[tid - 1];
        cnt[tid * 2] = excl;
        cnt[tid * 2 + 1] = excl + v0;
        g_off[nbase + tid * 2] = e0 + excl;
        g_off[nbase + tid * 2 + 1] = e0 + excl + v0;
        if (g == BG - 1 && tid == 255) g_off[NN] = E;
        __syncthreads();
        for (int e = e0 + tid; e < e0 + EPG; e += 256) {
            int d = dst[e] - nbase;
            int s = src[e];
            int p = atomicAdd(&cnt[d], 1);
            g_csr[e0 + p] = s;
        }
    } else if (bid < 544) {
        int idx = bid - 32;
        int bk = (idx & 7) * 32;
        int bn = (idx >> 3) * 32;
        int tx = tid & 31, ty = tid >> 5;
#pragma unroll
        for (int i = 0; i < 4; i++) {
            int k = bk + ty + i * 8;
            t[ty + i * 8][tx] = Wp[(size_t)k * ACOLS + bn + tx];
        }
        __syncthreads();
#pragma unroll
        for (int i = 0; i < 4; i++) {
            int n = bn + ty + i * 8;
            float v = t[tx][ty + i * 8];
            __nv_bfloat16 hh = __float2bfloat16(v);
            __nv_bfloat16 ll = __float2bfloat16(v - __bfloat162float(hh));
            g_WpTh[(size_t)n * DX + bk + tx] = hh;
            g_WpTl[(size_t)n * DX + bk + tx] = ll;
        }
    } else if (bid < 801) {
        __shared__ float red2[256];
        float* r = red2;
        int a = bid - 544;
        float s = 0.f;
        if (a < DX) {
            for (int j = tid; j < ACOLS; j += 256)
                s += Wp[(size_t)a * ACOLS + j] * bp[j];
        } else {
            for (int j = tid; j < ACOLS; j += 256) {
                float b = bp[j]; s += b * b;
            }
        }
        r[tid] = s;
        __syncthreads();
        for (int o = 128; o > 0; o >>= 1) {
            if (tid < o) r[tid] += r[tid + o];
            __syncthreads();
        }
        if (tid == 0) {
            if (a < DX) g_u[a] = r[0];
            else g_cb = r[0];
        }
    } else if (bid < 833) {
        int idx = bid - 801;
        int bk = (idx & 7) * 32;
        int bn = (idx >> 3) * 32;
        int tx = tid & 31, ty = tid >> 5;
#pragma unroll
        for (int i = 0; i < 4; i++) {
            int k = bk + ty + i * 8;
            t[ty + i * 8][tx] = Wf[(size_t)k * DOUT + bn + tx];
        }
        __syncthreads();
#pragma unroll
        for (int i = 0; i < 4; i++) {
            int n = bn + ty + i * 8;
            float v = t[tx][ty + i * 8];
            __nv_bfloat16 hh = __float2bfloat16(v);
            __nv_bfloat16 ll = __float2bfloat16(v - __bfloat162float(hh));
            g_WTh[(size_t)n * DX + bk + tx] = hh;
            g_WTl[(size_t)n * DX + bk + tx] = ll;
        }
    } else {
        int idx = bid - 833;  // 0..15
        for (int j = idx * 1024 + tid; j < (idx + 1) * 1024; j += 256)
            g_q[j] = 0.f;
    }
}

// ---------------- neighbor mean + bundle build + bf16 split ----------------
__device__ __forceinline__ void split_store(__nv_bfloat16* Hp, __nv_bfloat16* Lp,
                                            float4 v) {
    __nv_bfloat16 h[4], l[4];
    float f[4] = {v.x, v.y, v.z, v.w};
#pragma unroll
    for (int i = 0; i < 4; i++) {
        h[i] = __float2bfloat16(f[i]);
        l[i] = __float2bfloat16(f[i] - __bfloat162float(h[i]));
    }
    *(uint2*)Hp = *(uint2*)h;
    *(uint2*)Lp = *(uint2*)l;
}

__global__ void k_agg(const float* __restrict__ h) {
    int w = (blockIdx.x * blockDim.x + threadIdx.x) >> 5;
    int l = threadIdx.x & 31;
    if (w >= NN) return;
    int b = g_off[w], e = g_off[w + 1];
    float4 acc = make_float4(0.f, 0.f, 0.f, 0.f);
    int t = b;
    for (; t + 4 <= e; t += 4) {
        int s0 = g_csr[t], s1 = g_csr[t + 1], s2 = g_csr[t + 2], s3 = g_csr[t + 3];
        float4 v0 = *(const float4*)(h + (size_t)s0 * DIN + l * 4);
        float4 v1 = *(const float4*)(h + (size_t)s1 * DIN + l * 4);
        float4 v2 = *(const float4*)(h + (size_t)s2 * DIN + l * 4);
        float4 v3 = *(const float4*)(h + (size_t)s3 * DIN + l * 4);
        acc.x += (v0.x + v1.x) + (v2.x + v3.x);
        acc.y += (v0.y + v1.y) + (v2.y + v3.y);
        acc.z += (v0.z + v1.z) + (v2.z + v3.z);
        acc.w += (v0.w + v1.w) + (v2.w + v3.w);
    }
    for (; t < e; t++) {
        int s = g_csr[t];
        float4 v = *(const float4*)(h + (size_t)s * DIN + l * 4);
        acc.x += v.x; acc.y += v.y; acc.z += v.z; acc.w += v.w;
    }
    float inv = 1.f / fmaxf((float)(e - b), 1.f);
    float4 own = *(const float4*)(h + (size_t)w * DIN + l * 4);
    acc.x *= inv; acc.y *= inv; acc.z *= inv; acc.w *= inv;
    size_t base0 = (size_t)w * DX + l * 4;
    size_t base1 = base0 + DIN;
    split_store(g_Xh + base0, g_Xl + base0, own);
    split_store(g_Xh + base1, g_Xl + base1, acc);
}

// -------- M = Wp @ Wp^T via mma.sync; direct fp32 load + convert;
//          epilogue writes bf16-split M straight into WT[128:384) (M symmetric)
__global__ void __launch_bounds__(256, 1) k_M_mma(const float* __restrict__ Wp) {
    __shared__ __nv_bfloat16 Ah[64 * 64], Al[64 * 64], Bh[64 * 64], Bl[64 * 64];
    uint32_t sAh = smem_to_u32(Ah), sAl = smem_to_u32(Al);
    uint32_t sBh = smem_to_u32(Bh), sBl = smem_to_u32(Bl);
    int tid = threadIdx.x, l = tid & 31, wid = tid >> 5;
    int a0 = blockIdx.x * 64, b0 = blockIdx.y * 64;
    int warp_m = wid & 3, warp_n = wid >> 2;

    float acc[4][4];
#pragma unroll
    for (int a = 0; a < 4; a++)
#pragma unroll
        for (int c = 0; c < 4; c++) acc[a][c] = 0.f;

    // loader: 512 chunks of 8 floats -> 16B bf16 per array; 2 iters of 256 thr
    int rA = warp_m * 16 + (l & 7) + ((l >> 3) & 1) * 8;
    int kA = (l >> 4) * 16;
    int rB = warp_n * 32 + (l & 7) + ((l >> 4) & 1) * 8;
    int kB = ((l >> 3) & 1) * 16;

    for (int kc = 0; kc < 32; kc++) {
        int kbase = kc * 64;
#pragma unroll
        for (int i = 0; i < 2; i++) {
            int idx = tid + i * 256;       // 0..511
            int row = idx >> 3;            // 0..63
            int colf = (idx & 7) * 8;      // float col 0..56
            uint32_t so = SMEM_SWIZZLE_128B((uint32_t)(row * 128 + colf * 2));
            const float* pa = Wp + (size_t)(a0 + row) * ACOLS + kbase + colf;
            const float* pb = Wp + (size_t)(b0 + row) * ACOLS + kbase + colf;
            float4 va0 = *(const float4*)pa;
            float4 va1 = *(const float4*)(pa + 4);
            float4 vb0 = *(const float4*)pb;
            float4 vb1 = *(const float4*)(pb + 4);
            __nv_bfloat16 hh[8], ll[8];
            float fa[8] = {va0.x, va0.y, va0.z, va0.w, va1.x, va1.y, va1.z, va1.w};
#pragma unroll
            for (int j = 0; j < 8; j++) {
                hh[j] = __float2bfloat16(fa[j]);
                ll[j] = __float2bfloat16(fa[j] - __bfloat162float(hh[j]));
            }
            *(uint4*)((char*)Ah + so) = *(uint4*)hh;
            *(uint4*)((char*)Al + so) = *(uint4*)ll;
            float fb[8] = {vb0.x, vb0.y, vb0.z, vb0.w, vb1.x, vb1.y, vb1.z, vb1.w};
#pragma unroll
            for (int j = 0; j < 8; j++) {
                hh[j] = __float2bfloat16(fb[j]);
                ll[j] = __float2bfloat16(fb[j] - __bfloat162float(hh[j]));
            }
            *(uint4*)((char*)Bh + so) = *(uint4*)hh;
            *(uint4*)((char*)Bl + so) = *(uint4*)ll;
        }
        __syncthreads();
#pragma unroll
        for (int ks = 0; ks < 4; ks++) {
            uint32_t aH[4], aL[4], bH[2][4], bL[2][4];
            {
                uint32_t off = SMEM_SWIZZLE_128B((uint32_t)(rA * 128 + ks * 32 + kA));
                ldsm4(aH, sAh + off);
                ldsm4(aL, sAl + off);
            }
#pragma unroll
            for (int ni = 0; ni < 2; ni++) {
                uint32_t off =
                    SMEM_SWIZZLE_128B((uint32_t)((rB + ni * 16) * 128 + ks * 32 + kB));
                ldsm4(bH[ni], sBh + off);
                ldsm4(bL[ni], sBl + off);
            }
#pragma unroll
            for (int nj = 0; nj < 4; nj++) {
                uint32_t* bh = &bH[nj >> 1][(nj & 1) * 2];
                uint32_t* bl = &bL[nj >> 1][(nj & 1) * 2];
                mma_bf16(acc[nj], aH, bh);
                mma_bf16(acc[nj], aL, bh);
                mma_bf16(acc[nj], aH, bl);
            }
        }
        __syncthreads();
    }
    // epilogue: M[r][c] -> WT[128+r][c] (M symmetric, no transpose needed)
#pragma unroll
    for (int nj = 0; nj < 4; nj++) {
        int r0 = a0 + warp_m * 16 + (l >> 2);
        int c = b0 + warp_n * 32 + nj * 8 + (l & 3) * 2;
#pragma unroll
        for (int half = 0; half < 2; half++) {
            int r = r0 + half * 8;
            float v0 = acc[nj][half * 2 + 0];
            float v1 = acc[nj][half * 2 + 1];
            __nv_bfloat16 h0 = __float2bfloat16(v0);
            __nv_bfloat16 h1 = __float2bfloat16(v1);
            __nv_bfloat16 l0 = __float2bfloat16(v0 - __bfloat162float(h0));
            __nv_bfloat16 l1 = __float2bfloat16(v1 - __bfloat162float(h1));
            __nv_bfloat162 hp, lp;
            hp.x = h0; hp.y = h1;
            lp.x = l0; lp.y = l1;
            *(__nv_bfloat162*)(g_WTh + (size_t)(128 + r) * DX + c) = hp;
            *(__nv_bfloat162*)(g_WTl + (size_t)(128 + r) * DX + c) = lp;
        }
    }
}

// ---------------- main GEMM via mma.sync (bf16 split-2), cp.async dbuf ------
#define KC 64
#define BUF_BYTES 65536
#define GA_H 0
#define GA_L 16384
#define GB_H 32768
#define GB_L 49152
#define SMEM_G (2 * BUF_BYTES)

__global__ void __launch_bounds__(256, 1) k_gemm_mma() {
    extern __shared__ char smem[];
    uint32_t sb = smem_to_u32(smem);
    int tid = threadIdx.x, l = tid & 31, wid = tid >> 5;
    int n0 = blockIdx.x * 128, m0 = blockIdx.y * 128;
    int warp_m = wid & 1, warp_n = wid >> 1;

    float acc[4][4][4];
#pragma unroll
    for (int a = 0; a < 4; a++)
#pragma unroll
        for (int b = 0; b < 4; b++)
#pragma unroll
            for (int c = 0; c < 4; c++) acc[a][b][c] = 0.f;

    int ldr[4], ldc[4];
#pragma unroll
    for (int i = 0; i < 4; i++) {
        int idx = tid + i * 256;
        ldr[i] = idx >> 3;
        ldc[i] = (idx & 7) * 16;
    }
    int rA = warp_m * 64 + (l & 7) + ((l >> 3) & 1) * 8;
    int kA = (l >> 4) * 16;
    int rB = warp_n * 32 + (l & 7) + ((l >> 4) & 1) * 8;
    int kB = ((l >> 3) & 1) * 16;

    {
#pragma unroll
        for (int i = 0; i < 4; i++) {
            int row = ldr[i];
            uint32_t so = SMEM_SWIZZLE_128B((uint32_t)(row * 128 + ldc[i]));
            size_t gA = (size_t)(m0 + row) * DX + (ldc[i] >> 1);
            size_t gB = (size_t)(n0 + row) * DX + (ldc[i] >> 1);
            cp16(sb + GA_H + so, g_Xh + gA);
            cp16(sb + GA_L + so, g_Xl + gA);
            cp16(sb + GB_H + so, g_WTh + gB);
            cp16(sb + GB_L + so, g_WTl + gB);
        }
        CP_COMMIT();
    }

    for (int c = 0; c < 4; c++) {
        uint32_t base = (uint32_t)(c & 1) * BUF_BYTES;
        if (c < 3) {
            uint32_t nb = (uint32_t)((c + 1) & 1) * BUF_BYTES;
            int koff = (c + 1) * KC;
#pragma unroll
            for (int i = 0; i < 4; i++) {
                int row = ldr[i];
                uint32_t so = SMEM_SWIZZLE_128B((uint32_t)(row * 128 + ldc[i]));
                size_t gA = (size_t)(m0 + row) * DX + koff + (ldc[i] >> 1);
                size_t gB = (size_t)(n0 + row) * DX + koff + (ldc[i] >> 1);
                cp16(sb + nb + GA_H + so, g_Xh + gA);
                cp16(sb + nb + GA_L + so, g_Xl + gA);
                cp16(sb + nb + GB_H + so, g_WTh + gB);
                cp16(sb + nb + GB_L + so, g_WTl + gB);
            }
            CP_COMMIT();
            CP_WAIT(1);
        } else {
            CP_WAIT(0);
        }
        __syncthreads();
#pragma unroll
        for (int ks = 0; ks < 4; ks++) {
            uint32_t aH[4][4], aL[4][4], bH[2][4], bL[2][4];
#pragma unroll
            for (int mi = 0; mi < 4; mi++) {
                uint32_t off =
                    SMEM_SWIZZLE_128B((uint32_t)((rA + mi * 16) * 128 + ks * 32 + kA));
                ldsm4(aH[mi], sb + base + GA_H + off);
                ldsm4(aL[mi], sb + base + GA_L + off);
            }
#pragma unroll
            for (int ni = 0; ni < 2; ni++) {
                uint32_t off =
                    SMEM_SWIZZLE_128B((uint32_t)((rB + ni * 16) * 128 + ks * 32 + kB));
                ldsm4(bH[ni], sb + base + GB_H + off);
                ldsm4(bL[ni], sb + base + GB_L + off);
            }
#pragma unroll
            for (int mi = 0; mi < 4; mi++)
#pragma unroll
                for (int nj = 0; nj < 4; nj++) {
                    uint32_t* bh = &bH[nj >> 1][(nj & 1) * 2];
                    uint32_t* bl = &bL[nj >> 1][(nj & 1) * 2];
                    mma_bf16(acc[mi][nj], aH[mi], bh);
                    mma_bf16(acc[mi][nj], aL[mi], bh);
                    mma_bf16(acc[mi][nj], aH[mi], bl);
                }
        }
        __syncthreads();
    }

    if (blockIdx.x == 0) {
#pragma unroll
        for (int mi = 0; mi < 4; mi++)
#pragma unroll
            for (int nj = 0; nj < 4; nj++) {
                int row = m0 + warp_m * 64 + mi * 16 + (l >> 2);
                int col = warp_n * 32 + nj * 8 + (l & 3) * 2;
                *(float2*)(g_C + (size_t)row * 128 + col) =
                    make_float2(acc[mi][nj][0], acc[mi][nj][1]);
                *(float2*)(g_C + (size_t)(row + 8) * 128 + col) =
                    make_float2(acc[mi][nj][2], acc[mi][nj][3]);
            }
    } else {
        float qr0[4] = {0.f, 0.f, 0.f, 0.f};
        float qr1[4] = {0.f, 0.f, 0.f, 0.f};
#pragma unroll
        for (int mi = 0; mi < 4; mi++) {
            int row = m0 + warp_m * 64 + mi * 16 + (l >> 2);
#pragma unroll
            for (int nj = 0; nj < 4; nj++) {
                int colX = (n0 - 128) + warp_n * 32 + nj * 8 + (l & 3) * 2;
                __nv_bfloat162 h01 = *(const __nv_bfloat162*)(g_Xh + (size_t)row * DX + colX);
                __nv_bfloat162 l01 = *(const __nv_bfloat162*)(g_Xl + (size_t)row * DX + colX);
                __nv_bfloat162 h23 = *(const __nv_bfloat162*)(g_Xh + (size_t)(row + 8) * DX + colX);
                __nv_bfloat162 l23 = *(const __nv_bfloat162*)(g_Xl + (size_t)(row + 8) * DX + colX);
                float2 hf01 = __bfloat1622float2(h01), lf01 = __bfloat1622float2(l01);
                float2 hf23 = __bfloat1622float2(h23), lf23 = __bfloat1622float2(l23);
                qr0[mi] += (hf01.x + lf01.x) * acc[mi][nj][0] +
                           (hf01.y + lf01.y) * acc[mi][nj][1];
                qr1[mi] += (hf23.x + lf23.x) * acc[mi][nj][2] +
                           (hf23.y + lf23.y) * acc[mi][nj][3];
            }
        }
#pragma unroll
        for (int mi = 0; mi < 4; mi++) {
            qr0[mi] += __shfl_xor_sync(0xffffffffu, qr0[mi], 1);
            qr0[mi] += __shfl_xor_sync(0xffffffffu, qr0[mi], 2);
            qr1[mi] += __shfl_xor_sync(0xffffffffu, qr1[mi], 1);
            qr1[mi] += __shfl_xor_sync(0xffffffffu, qr1[mi], 2);
        }
        if ((l & 3) == 0) {
#pragma unroll
            for (int mi = 0; mi < 4; mi++) {
                int row = m0 + warp_m * 64 + mi * 16 + (l >> 2);
                atomicAdd(&g_q[row], qr0[mi]);
                atomicAdd(&g_q[row + 8], qr1[mi]);
            }
        }
    }
}

// ---------------- post: feat normalize+relu, pool norm reciprocal ----------------
__global__ void k_post(const float* __restrict__ bfeat) {
    int w = (blockIdx.x * blockDim.x + threadIdx.x) >> 5;
    int l = threadIdx.x & 31;
    if (w >= NN) return;
    const __nv_bfloat16* Xh = g_Xh + (size_t)w * DX;
    const __nv_bfloat16* Xl = g_Xl + (size_t)w * DX;
    float xu = 0.f;
#pragma unroll
    for (int r = 0; r < 4; r++) {
        int j = (l + 32 * r) * 2;
        __nv_bfloat162 h2 = *(const __nv_bfloat162*)(Xh + j);
        __nv_bfloat162 l2 = *(const __nv_bfloat162*)(Xl + j);
        float2 hf = __bfloat1622float2(h2), lf = __bfloat1622float2(l2);
        xu += (hf.x + lf.x) * g_u[j] + (hf.y + lf.y) * g_u[j + 1];
    }
#pragma unroll
    for (int o = 16; o > 0; o >>= 1)
        xu += __shfl_xor_sync(0xffffffffu, xu, o);
    float n2 = g_q[w] + 2.f * xu + g_cb;
    float rn = 1.f / fmaxf(sqrtf(fmaxf(n2, 0.f)), 1e-12f);
    if (l == 0) g_rnp[w] = rn;

    const float* Crow = g_C + (size_t)w * 128;
    float f[4];
    float s2 = 0.f;
#pragma unroll
    for (int r = 0; r < 4; r++) {
        int j = l + 32 * r;
        f[r] = Crow[j] + bfeat[j];
        s2 += f[r] * f[r];
    }
#pragma unroll
    for (int o = 16; o > 0; o >>= 1) s2 += __shfl_xor_sync(0xffffffffu, s2, o);
    float rf = 1.f / fmaxf(sqrtf(s2), 1e-12f);
#pragma unroll
    for (int r = 0; r < 4; r++)
        g_feat[(size_t)w * DOUT + l + 32 * r] = fmaxf(f[r] * rf, 0.f);
}

// ---------------- assign GEMM via mma.sync + fused softmax ----------------
#define AA_H 0
#define AA_L 16384
#define AB_H 32768
#define AB_L 40960
#define SMEM_A 49152

__global__ void __launch_bounds__(256, 1) k_assign_mma(const float* __restrict__ bp) {
    extern __shared__ char smem[];
    uint32_t sb = smem_to_u32(smem);
    int tid = threadIdx.x, l = tid & 31, wid = tid >> 5;
    int g = blockIdx.y;
    int n0g = g * NPER + blockIdx.x * 128;
    int warp_m = wid & 1, warp_n = wid >> 1;

    float acc[4][2][4];
#pragma unroll
    for (int a = 0; a < 4; a++)
#pragma unroll
        for (int b = 0; b < 2; b++)
#pragma unroll
            for (int c = 0; c < 4; c++) acc[a][b][c] = 0.f;

    int rA = warp_m * 64 + (l & 7) + ((l >> 3) & 1) * 8;
    int kA = (l >> 4) * 16;
    int rB = warp_n * 16 + (l & 7) + ((l >> 4) & 1) * 8;
    int kB = ((l >> 3) & 1) * 16;

    for (int c = 0; c < 4; c++) {
#pragma unroll
        for (int i = 0; i < 4; i++) {
            int idx = tid + i * 256;
            int row = idx >> 3, cb = (idx & 7) * 16;
            uint32_t so = SMEM_SWIZZLE_128B((uint32_t)(row * 128 + cb));
            size_t gA = (size_t)(n0g + row) * DX + c * KC + (cb >> 1);
            *(uint4*)(smem + AA_H + so) = *(const uint4*)(g_Xh + gA);
            *(uint4*)(smem + AA_L + so) = *(const uint4*)(g_Xl + gA);
        }
#pragma unroll
        for (int i = 0; i < 2; i++) {
            int idx = tid + i * 256;
            int row = idx >> 3, cb = (idx & 7) * 16;
            uint32_t so = SMEM_SWIZZLE_128B((uint32_t)(row * 128 + cb));
            size_t gB = (size_t)(g * KCL + row) * DX + c * KC + (cb >> 1);
            *(uint4*)(smem + AB_H + so) = *(const uint4*)(g_WpTh + gB);
            *(uint4*)(smem + AB_L + so) = *(const uint4*)(g_WpTl + gB);
        }
        __syncthreads();
#pragma unroll
        for (int ks = 0; ks < 4; ks++) {
            uint32_t aH[4][4], aL[4][4], bH[4], bL[4];
#pragma unroll
            for (int mi = 0; mi < 4; mi++) {
                uint32_t off =
                    SMEM_SWIZZLE_128B((uint32_t)((rA + mi * 16) * 128 + ks * 32 + kA));
                ldsm4(aH[mi], sb + AA_H + off);
                ldsm4(aL[mi], sb + AA_L + off);
            }
            {
                uint32_t off =
                    SMEM_SWIZZLE_128B((uint32_t)(rB * 128 + ks * 32 + kB));
                ldsm4(bH, sb + AB_H + off);
                ldsm4(bL, sb + AB_L + off);
            }
#pragma unroll
            for (int mi = 0; mi < 4; mi++)
#pragma unroll
                for (int nj = 0; nj < 2; nj++) {
                    const uint32_t* bh = &bH[nj * 2];
                    const uint32_t* bl = &bL[nj * 2];
                    mma_bf16(acc[mi][nj], aH[mi], bh);
                    mma_bf16(acc[mi][nj], aL[mi], bh);
                    mma_bf16(acc[mi][nj], aH[mi], bl);
                }
        }
        __syncthreads();
    }
    float(*Zs)[66] = (float(*)[66])smem;
#pragma unroll
    for (int mi = 0; mi < 4; mi++)
#pragma unroll
        for (int nj = 0; nj < 2; nj++) {
            int row = warp_m * 64 + mi * 16 + (l >> 2);
            int col = warp_n * 16 + nj * 8 + (l & 3) * 2;
            *(float2*)(&Zs[row][col]) = make_float2(acc[mi][nj][0], acc[mi][nj][1]);
            *(float2*)(&Zs[row + 8][col]) = make_float2(acc[mi][nj][2], acc[mi][nj][3]);
        }
    __syncthreads();

    for (int rr = 0; rr < 16; rr++) {
        int row = wid * 16 + rr;
        int node = n0g + row;
        float rn = g_rnp[node];
        float v0 = fmaxf((Zs[row][l] + bp[g * KCL + l]) * rn, 0.f);
        float v1 = fmaxf((Zs[row][l + 32] + bp[g * KCL + l + 32]) * rn, 0.f);
        float e0 = expf(v0), e1 = expf(v1);
        float t = e0 + e1;
#pragma unroll
        for (int o = 16; o > 0; o >>= 1) t += __shfl_xor_sync(0xffffffffu, t, o);
        float inv = 1.f / t;
        g_s[(size_t)node * KCL + l] = e0 * inv;
        g_s[(size_t)node * KCL + l + 32] = e1 * inv;
    }
}

// ---------------- fused pooling: gather a_s + h_new + adj blocks ----------------
#define SMEM_P 65536
__global__ void __launch_bounds__(256, 1) k_pool(float* __restrict__ out) {
    extern __shared__ char smemc[];
    float* Ss = (float*)smemc;            // [64][64]
    float* Ff = Ss + 64 * 64;             // [64][128]
    float* Aa = Ff + 64 * 128;            // [64][64]
    int g = blockIdx.y;
    int n0 = g * NPER + blockIdx.x * 64;
    int tid = threadIdx.x;
    int wid = tid >> 5, l = tid & 31;

#pragma unroll
    for (int q = 0; q < 16; q++) {
        int idx = tid + q * 256;
        Ss[idx] = g_s[(size_t)n0 * KCL + idx];
    }
#pragma unroll
    for (int q = 0; q < 32; q++) {
        int idx = tid + q * 256;
        Ff[idx] = g_feat[(size_t)n0 * DOUT + idx];
    }

    for (int r = 0; r < 8; r++) {
        int row = wid * 8 + r;
        int node = n0 + row;
        int b = g_off[node], e = g_off[node + 1];
        float a0 = 0.f, a1 = 0.f;
        int t = b;
        for (; t + 4 <= e; t += 4) {
            int s0 = g_csr[t], s1 = g_csr[t + 1], s2 = g_csr[t + 2], s3 = g_csr[t + 3];
            float p0 = g_s[(size_t)s0 * KCL + l], q0 = g_s[(size_t)s0 * KCL + 32 + l];
            float p1 = g_s[(size_t)s1 * KCL + l], q1 = g_s[(size_t)s1 * KCL + 32 + l];
            float p2 = g_s[(size_t)s2 * KCL + l], q2 = g_s[(size_t)s2 * KCL + 32 + l];
            float p3 = g_s[(size_t)s3 * KCL + l], q3 = g_s[(size_t)s3 * KCL + 32 + l];
            a0 += (p0 + p1) + (p2 + p3);
            a1 += (q0 + q1) + (q2 + q3);
        }
        for (; t < e; t++) {
            int s = g_csr[t];
            a0 += g_s[(size_t)s * KCL + l];
            a1 += g_s[(size_t)s * KCL + 32 + l];
        }
        Aa[row * 64 + l] = a0;
        Aa[row * 64 + 32 + l] = a1;
    }
    __syncthreads();

    {
        int tx = tid & 31, ty = tid >> 5;
        unsigned long long acc[8][2];
#pragma unroll
        for (int r = 0; r < 8; r++) { acc[r][0] = 0ull; acc[r][1] = 0ull; }
        for (int k = 0; k < 64; k++) {
            float4 f4 = *(float4*)(&Ff[k * 128 + tx * 4]);
            unsigned long long fp0 = pk2(f4.x, f4.y);
            unsigned long long fp1 = pk2(f4.z, f4.w);
#pragma unroll
            for (int r = 0; r < 8; r++) {
                float a = Ss[k * 64 + ty * 8 + r];
                unsigned long long ab = pk2(a, a);
                fma2(acc[r][0], ab, fp0);
                fma2(acc[r][1], ab, fp1);
            }
        }
#pragma unroll
        for (int r = 0; r < 8; r++) {
            float2 u0 = up2(acc[r][0]), u1 = up2(acc[r][1]);
            float v[4] = {u0.x, u0.y, u1.x, u1.y};
            size_t base = (size_t)ADJ_OFF + (size_t)(g * KCL + ty * 8 + r) * DOUT + tx * 4;
#pragma unroll
            for (int j = 0; j < 4; j++) atomicAdd(out + base + j, v[j]);
        }
    }

    {
        int tx = tid & 15, ty = tid >> 4;
        unsigned long long acc[2][4];
#pragma unroll
        for (int p = 0; p < 2; p++)
#pragma unroll
            for (int j = 0; j < 4; j++) acc[p][j] = 0ull;
        for (int k = 0; k < 64; k++) {
            float4 a4 = *(float4*)(&Ss[k * 64 + ty * 4]);
            unsigned long long ap0 = pk2(a4.x, a4.y);
            unsigned long long ap1 = pk2(a4.z, a4.w);
            float4 b4 = *(float4*)(&Aa[k * 64 + tx * 4]);
            float bsc[4] = {b4.x, b4.y, b4.z, b4.w};
#pragma unroll
            for (int j = 0; j < 4; j++) {
                unsigned long long bb = pk2(bsc[j], bsc[j]);
                fma2(acc[0][j], ap0, bb);
                fma2(acc[1][j], ap1, bb);
            }
        }
#pragma unroll
        for (int p = 0; p < 2; p++)
#pragma unroll
            for (int c = 0; c < 2; c++) {
                int row = g * KCL + ty * 4 + 2 * p + c;
                size_t base = (size_t)row * 2048 + g * KCL + tx * 4;
#pragma unroll
                for (int j = 0; j < 4; j++) {
                    float2 u = up2(acc[p][j]);
                    atomicAdd(out + base + j, c == 0 ? u.x : u.y);
                }
            }
    }
}

// ---------------- launch ----------------
extern "C" void kernel_launch(void* const* d_in, const int* in_sizes, int n_in,
                              void* d_out, int out_size) {
    const float* h  = (const float*)d_in[0];
    const float* Wf = (const float*)d_in[1];
    const float* bf = (const float*)d_in[2];
    const float* Wp = (const float*)d_in[3];
    const float* bp = (const float*)d_in[4];
    const int* esrc = (const int*)d_in[5];
    const int* edst = (const int*)d_in[6];
    int E = in_sizes[5];
    float* out = (float*)d_out;

    cudaFuncSetAttribute(k_gemm_mma, cudaFuncAttributeMaxDynamicSharedMemorySize,
                         SMEM_G);
    cudaFuncSetAttribute(k_assign_mma, cudaFuncAttributeMaxDynamicSharedMemorySize,
                         SMEM_A);
    cudaFuncSetAttribute(k_pool, cudaFuncAttributeMaxDynamicSharedMemorySize,
                         SMEM_P);

    cudaMemsetAsync(d_out, 0, (size_t)out_size * sizeof(float));
    k_setup<<<849, 256>>>(Wf, Wp, bp, esrc, edst, E);
    k_M_mma<<<dim3(4, 4), 256>>>(Wp);
    k_agg<<<2048, 256>>>(h);
    k_gemm_mma<<<dim3(3, 128), 256, SMEM_G>>>();
    k_post<<<2048, 256>>>(bf);
    k_assign_mma<<<dim3(4, BG), 256, SMEM_A>>>(bp);
    k_pool<<<dim3(8, BG), 256, SMEM_P>>>(out);
}

// round 13
// speedup vs baseline: 1.1909x; 1.1909x over previous
#include <cuda_runtime.h>
#include <cuda_bf16.h>
#include <stdint.h>
#include <math.h>

#define NN 16384
#define DIN 128
#define DX 256
#define DOUT 128
#define BG 32
#define NPER 512
#define KCL 64
#define ACOLS 2048
#define EMAX 262144
#define ADJ_OFF (2048*2048)

// ================= helpers =================
__device__ __forceinline__ uint32_t smem_to_u32(const void* p) {
    uint32_t a;
    asm("{ .reg .u64 t; cvta.to.shared.u64 t, %1; cvt.u32.u64 %0, t; }"
        : "=r"(a) : "l"(p));
    return a;
}
#define SMEM_SWIZZLE_128B(o) ((o) ^ (((o) >> 3) & 0x70))

__device__ __forceinline__ void ldsm4(uint32_t* r, uint32_t addr) {
    asm volatile("ldmatrix.sync.aligned.m8n8.x4.shared.b16 {%0,%1,%2,%3}, [%4];"
                 : "=r"(r[0]), "=r"(r[1]), "=r"(r[2]), "=r"(r[3]) : "r"(addr));
}
__device__ __forceinline__ void mma_bf16(float* d, const uint32_t* a,
                                         const uint32_t* b) {
    asm volatile(
        "mma.sync.aligned.m16n8k16.row.col.f32.bf16.bf16.f32 "
        "{%0,%1,%2,%3}, {%4,%5,%6,%7}, {%8,%9}, {%0,%1,%2,%3};"
        : "+f"(d[0]), "+f"(d[1]), "+f"(d[2]), "+f"(d[3])
        : "r"(a[0]), "r"(a[1]), "r"(a[2]), "r"(a[3]), "r"(b[0]), "r"(b[1]));
}

// ---------------- f32x2 packed-math helpers ----------------
__device__ __forceinline__ unsigned long long pk2(float lo, float hi) {
    unsigned long long r;
    asm("mov.b64 %0, {%1, %2};" : "=l"(r) : "f"(lo), "f"(hi));
    return r;
}
__device__ __forceinline__ void fma2(unsigned long long& d, unsigned long long a,
                                     unsigned long long b) {
    asm("fma.rn.f32x2 %0, %1, %2, %0;" : "+l"(d) : "l"(a), "l"(b));
}
__device__ __forceinline__ float2 up2(unsigned long long v) {
    float lo, hi;
    asm("mov.b64 {%0, %1}, %2;" : "=f"(lo), "=f"(hi) : "l"(v));
    return make_float2(lo, hi);
}

// ---------------- device scratch ----------------
__device__ int   g_off[NN + 1];
__device__ int   g_csr[EMAX];
__device__ __nv_bfloat16 g_Xh[NN * DX];   // bf16 hi of [h | h_neigh]
__device__ __nv_bfloat16 g_Xl[NN * DX];   // bf16 lo
__device__ __nv_bfloat16 g_WTh[384 * DX];     // WT[n][k] hi ([0:128)=Wf^T, [128:384)=M)
__device__ __nv_bfloat16 g_WTl[384 * DX];     // WT[n][k] lo
__device__ __nv_bfloat16 g_WpTh[ACOLS * DX];  // WpT[c][k] hi
__device__ __nv_bfloat16 g_WpTl[ACOLS * DX];  // WpT[c][k] lo
__device__ float g_M[DX * DX];            // W_pool W_pool^T (fp32, split-K atomics)
__device__ float g_C[NN * 128];           // feat pre-activation
__device__ float g_q[NN];                 // x^T M x
__device__ float g_feat[NN * DOUT];
__device__ float g_rnp[NN];
__device__ float g_s[NN * KCL];
__device__ float g_u[DX];
__device__ float g_cb;

// ================== k_setup: all independent preprocessing ==================
// blocks [0,32): per-graph CSR
// blocks [32,544): WpT transpose + bf16 split
// blocks [544,801): u/cb reductions
// blocks [801,833): Wf transpose-split -> WT[0:128)
// blocks [833,849): zero g_q + g_M
__global__ void __launch_bounds__(256, 1) k_setup(
    const float* __restrict__ Wf, const float* __restrict__ Wp,
    const float* __restrict__ bp, const int* __restrict__ src,
    const int* __restrict__ dst, int E) {
    __shared__ int cnt[NPER];
    __shared__ int part[256];
    __shared__ float t[32][33];
    int bid = blockIdx.x;
    int tid = threadIdx.x;

    if (bid < 32) {
        int g = bid;
        int EPG = E / BG;
        int e0 = g * EPG;
        int nbase = g * NPER;
#pragma unroll
        for (int i = tid; i < NPER; i += 256) cnt[i] = 0;
        __syncthreads();
        for (int e = e0 + tid; e < e0 + EPG; e += 256)
            atomicAdd(&cnt[dst[e] - nbase], 1);
        __syncthreads();
        int v0 = cnt[tid * 2], v1 = cnt[tid * 2 + 1];
        part[tid] = v0 + v1;
        __syncthreads();
        for (int off = 1; off < 256; off <<= 1) {
            int v = 0;
            if (tid >= off) v = part[tid - off];
            __syncthreads();
            if (tid >= off) part[tid] += v;
            __syncthreads();
        }
        int excl = (tid == 0) ? 0 : part[tid - 1];
        cnt[tid * 2] = excl;
        cnt[tid * 2 + 1] = excl + v0;
        g_off[nbase + tid * 2] = e0 + excl;
        g_off[nbase + tid * 2 + 1] = e0 + excl + v0;
        if (g == BG - 1 && tid == 255) g_off[NN] = E;
        __syncthreads();
        for (int e = e0 + tid; e < e0 + EPG; e += 256) {
            int d = dst[e] - nbase;
            int s = src[e];
            int p = atomicAdd(&cnt[d], 1);
            g_csr[e0 + p] = s;
        }
    } else if (bid < 544) {
        int idx = bid - 32;
        int bk = (idx & 7) * 32;
        int bn = (idx >> 3) * 32;
        int tx = tid & 31, ty = tid >> 5;
#pragma unroll
        for (int i = 0; i < 4; i++) {
            int k = bk + ty + i * 8;
            t[ty + i * 8][tx] = Wp[(size_t)k * ACOLS + bn + tx];
        }
        __syncthreads();
#pragma unroll
        for (int i = 0; i < 4; i++) {
            int n = bn + ty + i * 8;
            float v = t[tx][ty + i * 8];
            __nv_bfloat16 hh = __float2bfloat16(v);
            __nv_bfloat16 ll = __float2bfloat16(v - __bfloat162float(hh));
            g_WpTh[(size_t)n * DX + bk + tx] = hh;
            g_WpTl[(size_t)n * DX + bk + tx] = ll;
        }
    } else if (bid < 801) {
        __shared__ float red2[256];
        float* r = red2;
        int a = bid - 544;
        float s = 0.f;
        if (a < DX) {
            for (int j = tid; j < ACOLS; j += 256)
                s += Wp[(size_t)a * ACOLS + j] * bp[j];
        } else {
            for (int j = tid; j < ACOLS; j += 256) {
                float b = bp[j]; s += b * b;
            }
        }
        r[tid] = s;
        __syncthreads();
        for (int o = 128; o > 0; o >>= 1) {
            if (tid < o) r[tid] += r[tid + o];
            __syncthreads();
        }
        if (tid == 0) {
            if (a < DX) g_u[a] = r[0];
            else g_cb = r[0];
        }
    } else if (bid < 833) {
        int idx = bid - 801;
        int bk = (idx & 7) * 32;
        int bn = (idx >> 3) * 32;
        int tx = tid & 31, ty = tid >> 5;
#pragma unroll
        for (int i = 0; i < 4; i++) {
            int k = bk + ty + i * 8;
            t[ty + i * 8][tx] = Wf[(size_t)k * DOUT + bn + tx];
        }
        __syncthreads();
#pragma unroll
        for (int i = 0; i < 4; i++) {
            int n = bn + ty + i * 8;
            float v = t[tx][ty + i * 8];
            __nv_bfloat16 hh = __float2bfloat16(v);
            __nv_bfloat16 ll = __float2bfloat16(v - __bfloat162float(hh));
            g_WTh[(size_t)n * DX + bk + tx] = hh;
            g_WTl[(size_t)n * DX + bk + tx] = ll;
        }
    } else {
        int idx = bid - 833;  // 0..15
        for (int j = idx * 1024 + tid; j < (idx + 1) * 1024; j += 256)
            g_q[j] = 0.f;
        for (int j = idx * 4096 + tid; j < (idx + 1) * 4096; j += 256)
            g_M[j] = 0.f;
    }
}

// ---- M = Wp @ Wp^T via mma.sync, split-K (64 CTAs), fp32-direct load ----
__global__ void __launch_bounds__(256, 1) k_M_mma(const float* __restrict__ Wp) {
    __shared__ __nv_bfloat16 Ah[64 * 64], Al[64 * 64], Bh[64 * 64], Bl[64 * 64];
    uint32_t sAh = smem_to_u32(Ah), sAl = smem_to_u32(Al);
    uint32_t sBh = smem_to_u32(Bh), sBl = smem_to_u32(Bl);
    int tid = threadIdx.x, l = tid & 31, wid = tid >> 5;
    int a0 = blockIdx.x * 64, b0 = blockIdx.y * 64, k0 = blockIdx.z * 512;
    int warp_m = wid & 3, warp_n = wid >> 2;

    float acc[4][4];
#pragma unroll
    for (int a = 0; a < 4; a++)
#pragma unroll
        for (int c = 0; c < 4; c++) acc[a][c] = 0.f;

    int rA = warp_m * 16 + (l & 7) + ((l >> 3) & 1) * 8;
    int kA = (l >> 4) * 16;
    int rB = warp_n * 32 + (l & 7) + ((l >> 4) & 1) * 8;
    int kB = ((l >> 3) & 1) * 16;

    for (int kc = 0; kc < 8; kc++) {
        int kbase = k0 + kc * 64;
#pragma unroll
        for (int i = 0; i < 2; i++) {
            int idx = tid + i * 256;
            int row = idx >> 3;
            int colf = (idx & 7) * 8;
            uint32_t so = SMEM_SWIZZLE_128B((uint32_t)(row * 128 + colf * 2));
            const float* pa = Wp + (size_t)(a0 + row) * ACOLS + kbase + colf;
            const float* pb = Wp + (size_t)(b0 + row) * ACOLS + kbase + colf;
            float4 va0 = *(const float4*)pa;
            float4 va1 = *(const float4*)(pa + 4);
            float4 vb0 = *(const float4*)pb;
            float4 vb1 = *(const float4*)(pb + 4);
            __nv_bfloat16 hh[8], ll[8];
            float fa[8] = {va0.x, va0.y, va0.z, va0.w, va1.x, va1.y, va1.z, va1.w};
#pragma unroll
            for (int j = 0; j < 8; j++) {
                hh[j] = __float2bfloat16(fa[j]);
                ll[j] = __float2bfloat16(fa[j] - __bfloat162float(hh[j]));
            }
            *(uint4*)((char*)Ah + so) = *(uint4*)hh;
            *(uint4*)((char*)Al + so) = *(uint4*)ll;
            float fb[8] = {vb0.x, vb0.y, vb0.z, vb0.w, vb1.x, vb1.y, vb1.z, vb1.w};
#pragma unroll
            for (int j = 0; j < 8; j++) {
                hh[j] = __float2bfloat16(fb[j]);
                ll[j] = __float2bfloat16(fb[j] - __bfloat162float(hh[j]));
            }
            *(uint4*)((char*)Bh + so) = *(uint4*)hh;
            *(uint4*)((char*)Bl + so) = *(uint4*)ll;
        }
        __syncthreads();
#pragma unroll
        for (int ks = 0; ks < 4; ks++) {
            uint32_t aH[4], aL[4], bH[2][4], bL[2][4];
            {
                uint32_t off = SMEM_SWIZZLE_128B((uint32_t)(rA * 128 + ks * 32 + kA));
                ldsm4(aH, sAh + off);
                ldsm4(aL, sAl + off);
            }
#pragma unroll
            for (int ni = 0; ni < 2; ni++) {
                uint32_t off =
                    SMEM_SWIZZLE_128B((uint32_t)((rB + ni * 16) * 128 + ks * 32 + kB));
                ldsm4(bH[ni], sBh + off);
                ldsm4(bL[ni], sBl + off);
            }
#pragma unroll
            for (int nj = 0; nj < 4; nj++) {
                uint32_t* bh = &bH[nj >> 1][(nj & 1) * 2];
                uint32_t* bl = &bL[nj >> 1][(nj & 1) * 2];
                mma_bf16(acc[nj], aH, bh);
                mma_bf16(acc[nj], aL, bh);
                mma_bf16(acc[nj], aH, bl);
            }
        }
        __syncthreads();
    }
#pragma unroll
    for (int nj = 0; nj < 4; nj++) {
        int arow = a0 + warp_m * 16 + (l >> 2);
        int bcol = b0 + warp_n * 32 + nj * 8 + (l & 3) * 2;
        atomicAdd(&g_M[arow * DX + bcol], acc[nj][0]);
        atomicAdd(&g_M[arow * DX + bcol + 1], acc[nj][1]);
        atomicAdd(&g_M[(arow + 8) * DX + bcol], acc[nj][2]);
        atomicAdd(&g_M[(arow + 8) * DX + bcol + 1], acc[nj][3]);
    }
}

// ---------------- neighbor mean + bf16 split; tail blocks: M -> WT split ----
__device__ __forceinline__ void split_store(__nv_bfloat16* Hp, __nv_bfloat16* Lp,
                                            float4 v) {
    __nv_bfloat16 h[4], l[4];
    float f[4] = {v.x, v.y, v.z, v.w};
#pragma unroll
    for (int i = 0; i < 4; i++) {
        h[i] = __float2bfloat16(f[i]);
        l[i] = __float2bfloat16(f[i] - __bfloat162float(h[i]));
    }
    *(uint2*)Hp = *(uint2*)h;
    *(uint2*)Lp = *(uint2*)l;
}

__global__ void k_agg(const float* __restrict__ h) {
    if (blockIdx.x >= 2048) {
        // M symmetric: WT[128+r][c] = M[r][c], bf16 split. 64 blocks of 32x32.
        int idx = blockIdx.x - 2048;
        int br = (idx & 7) * 32;
        int bc = (idx >> 3) * 32;
        int tx = threadIdx.x & 31, ty = threadIdx.x >> 5;
#pragma unroll
        for (int i = 0; i < 4; i++) {
            int r = br + ty + i * 8;
            float v = g_M[r * DX + bc + tx];
            __nv_bfloat16 hh = __float2bfloat16(v);
            __nv_bfloat16 ll = __float2bfloat16(v - __bfloat162float(hh));
            g_WTh[(size_t)(128 + r) * DX + bc + tx] = hh;
            g_WTl[(size_t)(128 + r) * DX + bc + tx] = ll;
        }
        return;
    }
    int w = (blockIdx.x * blockDim.x + threadIdx.x) >> 5;
    int l = threadIdx.x & 31;
    int b = g_off[w], e = g_off[w + 1];
    float4 acc = make_float4(0.f, 0.f, 0.f, 0.f);
    int t = b;
    for (; t + 4 <= e; t += 4) {
        int s0 = g_csr[t], s1 = g_csr[t + 1], s2 = g_csr[t + 2], s3 = g_csr[t + 3];
        float4 v0 = *(const float4*)(h + (size_t)s0 * DIN + l * 4);
        float4 v1 = *(const float4*)(h + (size_t)s1 * DIN + l * 4);
        float4 v2 = *(const float4*)(h + (size_t)s2 * DIN + l * 4);
        float4 v3 = *(const float4*)(h + (size_t)s3 * DIN + l * 4);
        acc.x += (v0.x + v1.x) + (v2.x + v3.x);
        acc.y += (v0.y + v1.y) + (v2.y + v3.y);
        acc.z += (v0.z + v1.z) + (v2.z + v3.z);
        acc.w += (v0.w + v1.w) + (v2.w + v3.w);
    }
    for (; t < e; t++) {
        int s = g_csr[t];
        float4 v = *(const float4*)(h + (size_t)s * DIN + l * 4);
        acc.x += v.x; acc.y += v.y; acc.z += v.z; acc.w += v.w;
    }
    float inv = 1.f / fmaxf((float)(e - b), 1.f);
    float4 own = *(const float4*)(h + (size_t)w * DIN + l * 4);
    acc.x *= inv; acc.y *= inv; acc.z *= inv; acc.w *= inv;
    size_t base0 = (size_t)w * DX + l * 4;
    size_t base1 = base0 + DIN;
    split_store(g_Xh + base0, g_Xl + base0, own);
    split_store(g_Xh + base1, g_Xl + base1, acc);
}

// ------- main GEMM via mma.sync (bf16 split-2), 128x64 tiles, 2 CTA/SM -------
#define KC 64
#define GA_H 0
#define GA_L 16384
#define GB_H 32768
#define GB_L 40960
#define SMEM_G 49152

__global__ void __launch_bounds__(256, 2) k_gemm_mma() {
    extern __shared__ char smem[];
    uint32_t sb = smem_to_u32(smem);
    int tid = threadIdx.x, l = tid & 31, wid = tid >> 5;
    int n0 = blockIdx.x * 64, m0 = blockIdx.y * 128;
    int warp_m = wid & 1, warp_n = wid >> 1;

    float acc[4][2][4];
#pragma unroll
    for (int a = 0; a < 4; a++)
#pragma unroll
        for (int b = 0; b < 2; b++)
#pragma unroll
            for (int c = 0; c < 4; c++) acc[a][b][c] = 0.f;

    int rA = warp_m * 64 + (l & 7) + ((l >> 3) & 1) * 8;
    int kA = (l >> 4) * 16;
    int rB = warp_n * 16 + (l & 7) + ((l >> 4) & 1) * 8;
    int kB = ((l >> 3) & 1) * 16;

    for (int c = 0; c < 4; c++) {
#pragma unroll
        for (int i = 0; i < 4; i++) {
            int idx = tid + i * 256;
            int row = idx >> 3, cb = (idx & 7) * 16;
            uint32_t so = SMEM_SWIZZLE_128B((uint32_t)(row * 128 + cb));
            size_t gA = (size_t)(m0 + row) * DX + c * KC + (cb >> 1);
            *(uint4*)(smem + GA_H + so) = *(const uint4*)(g_Xh + gA);
            *(uint4*)(smem + GA_L + so) = *(const uint4*)(g_Xl + gA);
        }
#pragma unroll
        for (int i = 0; i < 2; i++) {
            int idx = tid + i * 256;
            int row = idx >> 3, cb = (idx & 7) * 16;
            uint32_t so = SMEM_SWIZZLE_128B((uint32_t)(row * 128 + cb));
            size_t gB = (size_t)(n0 + row) * DX + c * KC + (cb >> 1);
            *(uint4*)(smem + GB_H + so) = *(const uint4*)(g_WTh + gB);
            *(uint4*)(smem + GB_L + so) = *(const uint4*)(g_WTl + gB);
        }
        __syncthreads();
#pragma unroll
        for (int ks = 0; ks < 4; ks++) {
            uint32_t aH[4][4], aL[4][4], bH[4], bL[4];
#pragma unroll
            for (int mi = 0; mi < 4; mi++) {
                uint32_t off =
                    SMEM_SWIZZLE_128B((uint32_t)((rA + mi * 16) * 128 + ks * 32 + kA));
                ldsm4(aH[mi], sb + GA_H + off);
                ldsm4(aL[mi], sb + GA_L + off);
            }
            {
                uint32_t off =
                    SMEM_SWIZZLE_128B((uint32_t)(rB * 128 + ks * 32 + kB));
                ldsm4(bH, sb + GB_H + off);
                ldsm4(bL, sb + GB_L + off);
            }
#pragma unroll
            for (int mi = 0; mi < 4; mi++)
#pragma unroll
                for (int nj = 0; nj < 2; nj++) {
                    const uint32_t* bh = &bH[nj * 2];
                    const uint32_t* bl = &bL[nj * 2];
                    mma_bf16(acc[mi][nj], aH[mi], bh);
                    mma_bf16(acc[mi][nj], aL[mi], bh);
                    mma_bf16(acc[mi][nj], aH[mi], bl);
                }
        }
        __syncthreads();
    }

    if (blockIdx.x < 2) {
        // feat block: store C (stride 128)
#pragma unroll
        for (int mi = 0; mi < 4; mi++)
#pragma unroll
            for (int nj = 0; nj < 2; nj++) {
                int row = m0 + warp_m * 64 + mi * 16 + (l >> 2);
                int col = n0 + warp_n * 16 + nj * 8 + (l & 3) * 2;
                *(float2*)(g_C + (size_t)row * 128 + col) =
                    make_float2(acc[mi][nj][0], acc[mi][nj][1]);
                *(float2*)(g_C + (size_t)(row + 8) * 128 + col) =
                    make_float2(acc[mi][nj][2], acc[mi][nj][3]);
            }
    } else {
        // M block: q partials
        float qr0[4] = {0.f, 0.f, 0.f, 0.f};
        float qr1[4] = {0.f, 0.f, 0.f, 0.f};
#pragma unroll
        for (int mi = 0; mi < 4; mi++) {
            int row = m0 + warp_m * 64 + mi * 16 + (l >> 2);
#pragma unroll
            for (int nj = 0; nj < 2; nj++) {
                int colX = (n0 - 128) + warp_n * 16 + nj * 8 + (l & 3) * 2;
                __nv_bfloat162 h01 = *(const __nv_bfloat162*)(g_Xh + (size_t)row * DX + colX);
                __nv_bfloat162 l01 = *(const __nv_bfloat162*)(g_Xl + (size_t)row * DX + colX);
                __nv_bfloat162 h23 = *(const __nv_bfloat162*)(g_Xh + (size_t)(row + 8) * DX + colX);
                __nv_bfloat162 l23 = *(const __nv_bfloat162*)(g_Xl + (size_t)(row + 8) * DX + colX);
                float2 hf01 = __bfloat1622float2(h01), lf01 = __bfloat1622float2(l01);
                float2 hf23 = __bfloat1622float2(h23), lf23 = __bfloat1622float2(l23);
                qr0[mi] += (hf01.x + lf01.x) * acc[mi][nj][0] +
                           (hf01.y + lf01.y) * acc[mi][nj][1];
                qr1[mi] += (hf23.x + lf23.x) * acc[mi][nj][2] +
                           (hf23.y + lf23.y) * acc[mi][nj][3];
            }
        }
#pragma unroll
        for (int mi = 0; mi < 4; mi++) {
            qr0[mi] += __shfl_xor_sync(0xffffffffu, qr0[mi], 1);
            qr0[mi] += __shfl_xor_sync(0xffffffffu, qr0[mi], 2);
            qr1[mi] += __shfl_xor_sync(0xffffffffu, qr1[mi], 1);
            qr1[mi] += __shfl_xor_sync(0xffffffffu, qr1[mi], 2);
        }
        if ((l & 3) == 0) {
#pragma unroll
            for (int mi = 0; mi < 4; mi++) {
                int row = m0 + warp_m * 64 + mi * 16 + (l >> 2);
                atomicAdd(&g_q[row], qr0[mi]);
                atomicAdd(&g_q[row + 8], qr1[mi]);
            }
        }
    }
}

// ---------------- post: feat normalize+relu, pool norm reciprocal ----------------
__global__ void k_post(const float* __restrict__ bfeat) {
    int w = (blockIdx.x * blockDim.x + threadIdx.x) >> 5;
    int l = threadIdx.x & 31;
    if (w >= NN) return;
    const __nv_bfloat16* Xh = g_Xh + (size_t)w * DX;
    const __nv_bfloat16* Xl = g_Xl + (size_t)w * DX;
    float xu = 0.f;
#pragma unroll
    for (int r = 0; r < 4; r++) {
        int j = (l + 32 * r) * 2;
        __nv_bfloat162 h2 = *(const __nv_bfloat162*)(Xh + j);
        __nv_bfloat162 l2 = *(const __nv_bfloat162*)(Xl + j);
        float2 hf = __bfloat1622float2(h2), lf = __bfloat1622float2(l2);
        xu += (hf.x + lf.x) * g_u[j] + (hf.y + lf.y) * g_u[j + 1];
    }
#pragma unroll
    for (int o = 16; o > 0; o >>= 1)
        xu += __shfl_xor_sync(0xffffffffu, xu, o);
    float n2 = g_q[w] + 2.f * xu + g_cb;
    float rn = 1.f / fmaxf(sqrtf(fmaxf(n2, 0.f)), 1e-12f);
    if (l == 0) g_rnp[w] = rn;

    const float* Crow = g_C + (size_t)w * 128;
    float f[4];
    float s2 = 0.f;
#pragma unroll
    for (int r = 0; r < 4; r++) {
        int j = l + 32 * r;
        f[r] = Crow[j] + bfeat[j];
        s2 += f[r] * f[r];
    }
#pragma unroll
    for (int o = 16; o > 0; o >>= 1) s2 += __shfl_xor_sync(0xffffffffu, s2, o);
    float rf = 1.f / fmaxf(sqrtf(s2), 1e-12f);
#pragma unroll
    for (int r = 0; r < 4; r++)
        g_feat[(size_t)w * DOUT + l + 32 * r] = fmaxf(f[r] * rf, 0.f);
}

// ---------------- assign GEMM via mma.sync + fused softmax ----------------
#define AA_H 0
#define AA_L 16384
#define AB_H 32768
#define AB_L 40960
#define SMEM_A 49152

__global__ void __launch_bounds__(256, 2) k_assign_mma(const float* __restrict__ bp) {
    extern __shared__ char smem[];
    uint32_t sb = smem_to_u32(smem);
    int tid = threadIdx.x, l = tid & 31, wid = tid >> 5;
    int g = blockIdx.y;
    int n0g = g * NPER + blockIdx.x * 128;
    int warp_m = wid & 1, warp_n = wid >> 1;

    float acc[4][2][4];
#pragma unroll
    for (int a = 0; a < 4; a++)
#pragma unroll
        for (int b = 0; b < 2; b++)
#pragma unroll
            for (int c = 0; c < 4; c++) acc[a][b][c] = 0.f;

    int rA = warp_m * 64 + (l & 7) + ((l >> 3) & 1) * 8;
    int kA = (l >> 4) * 16;
    int rB = warp_n * 16 + (l & 7) + ((l >> 4) & 1) * 8;
    int kB = ((l >> 3) & 1) * 16;

    for (int c = 0; c < 4; c++) {
#pragma unroll
        for (int i = 0; i < 4; i++) {
            int idx = tid + i * 256;
            int row = idx >> 3, cb = (idx & 7) * 16;
            uint32_t so = SMEM_SWIZZLE_128B((uint32_t)(row * 128 + cb));
            size_t gA = (size_t)(n0g + row) * DX + c * KC + (cb >> 1);
            *(uint4*)(smem + AA_H + so) = *(const uint4*)(g_Xh + gA);
            *(uint4*)(smem + AA_L + so) = *(const uint4*)(g_Xl + gA);
        }
#pragma unroll
        for (int i = 0; i < 2; i++) {
            int idx = tid + i * 256;
            int row = idx >> 3, cb = (idx & 7) * 16;
            uint32_t so = SMEM_SWIZZLE_128B((uint32_t)(row * 128 + cb));
            size_t gB = (size_t)(g * KCL + row) * DX + c * KC + (cb >> 1);
            *(uint4*)(smem + AB_H + so) = *(const uint4*)(g_WpTh + gB);
            *(uint4*)(smem + AB_L + so) = *(const uint4*)(g_WpTl + gB);
        }
        __syncthreads();
#pragma unroll
        for (int ks = 0; ks < 4; ks++) {
            uint32_t aH[4][4], aL[4][4], bH[4], bL[4];
#pragma unroll
            for (int mi = 0; mi < 4; mi++) {
                uint32_t off =
                    SMEM_SWIZZLE_128B((uint32_t)((rA + mi * 16) * 128 + ks * 32 + kA));
                ldsm4(aH[mi], sb + AA_H + off);
                ldsm4(aL[mi], sb + AA_L + off);
            }
            {
                uint32_t off =
                    SMEM_SWIZZLE_128B((uint32_t)(rB * 128 + ks * 32 + kB));
                ldsm4(bH, sb + AB_H + off);
                ldsm4(bL, sb + AB_L + off);
            }
#pragma unroll
            for (int mi = 0; mi < 4; mi++)
#pragma unroll
                for (int nj = 0; nj < 2; nj++) {
                    const uint32_t* bh = &bH[nj * 2];
                    const uint32_t* bl = &bL[nj * 2];
                    mma_bf16(acc[mi][nj], aH[mi], bh);
                    mma_bf16(acc[mi][nj], aL[mi], bh);
                    mma_bf16(acc[mi][nj], aH[mi], bl);
                }
        }
        __syncthreads();
    }
    float(*Zs)[66] = (float(*)[66])smem;
#pragma unroll
    for (int mi = 0; mi < 4; mi++)
#pragma unroll
        for (int nj = 0; nj < 2; nj++) {
            int row = warp_m * 64 + mi * 16 + (l >> 2);
            int col = warp_n * 16 + nj * 8 + (l & 3) * 2;
            *(float2*)(&Zs[row][col]) = make_float2(acc[mi][nj][0], acc[mi][nj][1]);
            *(float2*)(&Zs[row + 8][col]) = make_float2(acc[mi][nj][2], acc[mi][nj][3]);
        }
    __syncthreads();

    for (int rr = 0; rr < 16; rr++) {
        int row = wid * 16 + rr;
        int node = n0g + row;
        float rn = g_rnp[node];
        float v0 = fmaxf((Zs[row][l] + bp[g * KCL + l]) * rn, 0.f);
        float v1 = fmaxf((Zs[row][l + 32] + bp[g * KCL + l + 32]) * rn, 0.f);
        float e0 = expf(v0), e1 = expf(v1);
        float t = e0 + e1;
#pragma unroll
        for (int o = 16; o > 0; o >>= 1) t += __shfl_xor_sync(0xffffffffu, t, o);
        float inv = 1.f / t;
        g_s[(size_t)node * KCL + l] = e0 * inv;
        g_s[(size_t)node * KCL + l + 32] = e1 * inv;
    }
}

// ---------------- fused pooling: gather a_s + h_new + adj blocks ----------------
#define SMEM_P 65536
__global__ void __launch_bounds__(256, 1) k_pool(float* __restrict__ out) {
    extern __shared__ char smemc[];
    float* Ss = (float*)smemc;            // [64][64]
    float* Ff = Ss + 64 * 64;             // [64][128]
    float* Aa = Ff + 64 * 128;            // [64][64]
    int g = blockIdx.y;
    int n0 = g * NPER + blockIdx.x * 64;
    int tid = threadIdx.x;
    int wid = tid >> 5, l = tid & 31;

#pragma unroll
    for (int q = 0; q < 16; q++) {
        int idx = tid + q * 256;
        Ss[idx] = g_s[(size_t)n0 * KCL + idx];
    }
#pragma unroll
    for (int q = 0; q < 32; q++) {
        int idx = tid + q * 256;
        Ff[idx] = g_feat[(size_t)n0 * DOUT + idx];
    }

    for (int r = 0; r < 8; r++) {
        int row = wid * 8 + r;
        int node = n0 + row;
        int b = g_off[node], e = g_off[node + 1];
        float a0 = 0.f, a1 = 0.f;
        int t = b;
        for (; t + 4 <= e; t += 4) {
            int s0 = g_csr[t], s1 = g_csr[t + 1], s2 = g_csr[t + 2], s3 = g_csr[t + 3];
            float p0 = g_s[(size_t)s0 * KCL + l], q0 = g_s[(size_t)s0 * KCL + 32 + l];
            float p1 = g_s[(size_t)s1 * KCL + l], q1 = g_s[(size_t)s1 * KCL + 32 + l];
            float p2 = g_s[(size_t)s2 * KCL + l], q2 = g_s[(size_t)s2 * KCL + 32 + l];
            float p3 = g_s[(size_t)s3 * KCL + l], q3 = g_s[(size_t)s3 * KCL + 32 + l];
            a0 += (p0 + p1) + (p2 + p3);
            a1 += (q0 + q1) + (q2 + q3);
        }
        for (; t < e; t++) {
            int s = g_csr[t];
            a0 += g_s[(size_t)s * KCL + l];
            a1 += g_s[(size_t)s * KCL + 32 + l];
        }
        Aa[row * 64 + l] = a0;
        Aa[row * 64 + 32 + l] = a1;
    }
    __syncthreads();

    {
        int tx = tid & 31, ty = tid >> 5;
        unsigned long long acc[8][2];
#pragma unroll
        for (int r = 0; r < 8; r++) { acc[r][0] = 0ull; acc[r][1] = 0ull; }
        for (int k = 0; k < 64; k++) {
            float4 f4 = *(float4*)(&Ff[k * 128 + tx * 4]);
            unsigned long long fp0 = pk2(f4.x, f4.y);
            unsigned long long fp1 = pk2(f4.z, f4.w);
#pragma unroll
            for (int r = 0; r < 8; r++) {
                float a = Ss[k * 64 + ty * 8 + r];
                unsigned long long ab = pk2(a, a);
                fma2(acc[r][0], ab, fp0);
                fma2(acc[r][1], ab, fp1);
            }
        }
#pragma unroll
        for (int r = 0; r < 8; r++) {
            float2 u0 = up2(acc[r][0]), u1 = up2(acc[r][1]);
            float v[4] = {u0.x, u0.y, u1.x, u1.y};
            size_t base = (size_t)ADJ_OFF + (size_t)(g * KCL + ty * 8 + r) * DOUT + tx * 4;
#pragma unroll
            for (int j = 0; j < 4; j++) atomicAdd(out + base + j, v[j]);
        }
    }

    {
        int tx = tid & 15, ty = tid >> 4;
        unsigned long long acc[2][4];
#pragma unroll
        for (int p = 0; p < 2; p++)
#pragma unroll
            for (int j = 0; j < 4; j++) acc[p][j] = 0ull;
        for (int k = 0; k < 64; k++) {
            float4 a4 = *(float4*)(&Ss[k * 64 + ty * 4]);
            unsigned long long ap0 = pk2(a4.x, a4.y);
            unsigned long long ap1 = pk2(a4.z, a4.w);
            float4 b4 = *(float4*)(&Aa[k * 64 + tx * 4]);
            float bsc[4] = {b4.x, b4.y, b4.z, b4.w};
#pragma unroll
            for (int j = 0; j < 4; j++) {
                unsigned long long bb = pk2(bsc[j], bsc[j]);
                fma2(acc[0][j], ap0, bb);
                fma2(acc[1][j], ap1, bb);
            }
        }
#pragma unroll
        for (int p = 0; p < 2; p++)
#pragma unroll
            for (int c = 0; c < 2; c++) {
                int row = g * KCL + ty * 4 + 2 * p + c;
                size_t base = (size_t)row * 2048 + g * KCL + tx * 4;
#pragma unroll
                for (int j = 0; j < 4; j++) {
                    float2 u = up2(acc[p][j]);
                    atomicAdd(out + base + j, c == 0 ? u.x : u.y);
                }
            }
    }
}

// ---------------- launch ----------------
extern "C" void kernel_launch(void* const* d_in, const int* in_sizes, int n_in,
                              void* d_out, int out_size) {
    const float* h  = (const float*)d_in[0];
    const float* Wf = (const float*)d_in[1];
    const float* bf = (const float*)d_in[2];
    const float* Wp = (const float*)d_in[3];
    const float* bp = (const float*)d_in[4];
    const int* esrc = (const int*)d_in[5];
    const int* edst = (const int*)d_in[6];
    int E = in_sizes[5];
    float* out = (float*)d_out;

    cudaFuncSetAttribute(k_gemm_mma, cudaFuncAttributeMaxDynamicSharedMemorySize,
                         SMEM_G);
    cudaFuncSetAttribute(k_assign_mma, cudaFuncAttributeMaxDynamicSharedMemorySize,
                         SMEM_A);
    cudaFuncSetAttribute(k_pool, cudaFuncAttributeMaxDynamicSharedMemorySize,
                         SMEM_P);

    cudaMemsetAsync(d_out, 0, (size_t)out_size * sizeof(float));
    k_setup<<<849, 256>>>(Wf, Wp, bp, esrc, edst, E);
    k_M_mma<<<dim3(4, 4, 4), 256>>>(Wp);
    k_agg<<<2048 + 64, 256>>>(h);
    k_gemm_mma<<<dim3(6, 128), 256, SMEM_G>>>();
    k_post<<<2048, 256>>>(bf);
    k_assign_mma<<<dim3(4, BG), 256, SMEM_A>>>(bp);
    k_pool<<<dim3(8, BG), 256, SMEM_P>>>(out);
}

// round 15
// speedup vs baseline: 1.2522x; 1.0515x over previous
#include <cuda_runtime.h>
#include <cuda_bf16.h>
#include <stdint.h>
#include <math.h>

#define NN 16384
#define DIN 128
#define DX 256
#define DOUT 128
#define BG 32
#define NPER 512
#define KCL 64
#define ACOLS 2048
#define EMAX 262144
#define ADJ_OFF (2048*2048)

// ================= helpers =================
__device__ __forceinline__ uint32_t smem_to_u32(const void* p) {
    uint32_t a;
    asm("{ .reg .u64 t; cvta.to.shared.u64 t, %1; cvt.u32.u64 %0, t; }"
        : "=r"(a) : "l"(p));
    return a;
}
#define SMEM_SWIZZLE_128B(o) ((o) ^ (((o) >> 3) & 0x70))

__device__ __forceinline__ void ldsm4(uint32_t* r, uint32_t addr) {
    asm volatile("ldmatrix.sync.aligned.m8n8.x4.shared.b16 {%0,%1,%2,%3}, [%4];"
                 : "=r"(r[0]), "=r"(r[1]), "=r"(r[2]), "=r"(r[3]) : "r"(addr));
}
__device__ __forceinline__ void mma_bf16(float* d, const uint32_t* a,
                                         const uint32_t* b) {
    asm volatile(
        "mma.sync.aligned.m16n8k16.row.col.f32.bf16.bf16.f32 "
        "{%0,%1,%2,%3}, {%4,%5,%6,%7}, {%8,%9}, {%0,%1,%2,%3};"
        : "+f"(d[0]), "+f"(d[1]), "+f"(d[2]), "+f"(d[3])
        : "r"(a[0]), "r"(a[1]), "r"(a[2]), "r"(a[3]), "r"(b[0]), "r"(b[1]));
}
__device__ __forceinline__ void cp16(uint32_t saddr, const void* g) {
    asm volatile("cp.async.cg.shared.global [%0], [%1], 16;"
                 :: "r"(saddr), "l"(g));
}
#define CP_COMMIT() asm volatile("cp.async.commit_group;" ::: "memory")
#define CP_WAIT(N)  asm volatile("cp.async.wait_group %0;" :: "n"(N) : "memory")

// ---------------- f32x2 packed-math helpers ----------------
__device__ __forceinline__ unsigned long long pk2(float lo, float hi) {
    unsigned long long r;
    asm("mov.b64 %0, {%1, %2};" : "=l"(r) : "f"(lo), "f"(hi));
    return r;
}
__device__ __forceinline__ void fma2(unsigned long long& d, unsigned long long a,
                                     unsigned long long b) {
    asm("fma.rn.f32x2 %0, %1, %2, %0;" : "+l"(d) : "l"(a), "l"(b));
}
__device__ __forceinline__ float2 up2(unsigned long long v) {
    float lo, hi;
    asm("mov.b64 {%0, %1}, %2;" : "=f"(lo), "=f"(hi) : "l"(v));
    return make_float2(lo, hi);
}

// ---------------- device scratch ----------------
__device__ int   g_off[NN + 1];
__device__ int   g_csr[EMAX];
__device__ __nv_bfloat16 g_Xh[NN * DX];   // bf16 hi of [h | h_neigh]
__device__ __nv_bfloat16 g_Xl[NN * DX];   // bf16 lo
__device__ __nv_bfloat16 g_WTh[384 * DX];     // WT[n][k] hi ([0:128)=Wf^T, [128:384)=M)
__device__ __nv_bfloat16 g_WTl[384 * DX];     // WT[n][k] lo
__device__ __nv_bfloat16 g_WpTh[ACOLS * DX];  // WpT[c][k] hi
__device__ __nv_bfloat16 g_WpTl[ACOLS * DX];  // WpT[c][k] lo
__device__ float g_M[DX * DX];            // W_pool W_pool^T (fp32, split-K atomics)
__device__ float g_C[NN * 128];           // feat pre-activation
__device__ float g_q[NN];                 // x^T M x
__device__ float g_feat[NN * DOUT];
__device__ float g_rnp[NN];
__device__ float g_s[NN * KCL];
__device__ float g_u[DX];
__device__ float g_cb;

// ================== k_setup: all independent preprocessing ==================
__global__ void __launch_bounds__(256, 1) k_setup(
    const float* __restrict__ Wf, const float* __restrict__ Wp,
    const float* __restrict__ bp, const int* __restrict__ src,
    const int* __restrict__ dst, int E) {
    __shared__ int cnt[NPER];
    __shared__ int part[256];
    __shared__ float t[32][33];
    int bid = blockIdx.x;
    int tid = threadIdx.x;

    if (bid < 32) {
        int g = bid;
        int EPG = E / BG;
        int e0 = g * EPG;
        int nbase = g * NPER;
#pragma unroll
        for (int i = tid; i < NPER; i += 256) cnt[i] = 0;
        __syncthreads();
        for (int e = e0 + tid; e < e0 + EPG; e += 256)
            atomicAdd(&cnt[dst[e] - nbase], 1);
        __syncthreads();
        int v0 = cnt[tid * 2], v1 = cnt[tid * 2 + 1];
        part[tid] = v0 + v1;
        __syncthreads();
        for (int off = 1; off < 256; off <<= 1) {
            int v = 0;
            if (tid >= off) v = part[tid - off];
            __syncthreads();
            if (tid >= off) part[tid] += v;
            __syncthreads();
        }
        int excl = (tid == 0) ? 0 : part[tid - 1];
        cnt[tid * 2] = excl;
        cnt[tid * 2 + 1] = excl + v0;
        g_off[nbase + tid * 2] = e0 + excl;
        g_off[nbase + tid * 2 + 1] = e0 + excl + v0;
        if (g == BG - 1 && tid == 255) g_off[NN] = E;
        __syncthreads();
        for (int e = e0 + tid; e < e0 + EPG; e += 256) {
            int d = dst[e] - nbase;
            int s = src[e];
            int p = atomicAdd(&cnt[d], 1);
            g_csr[e0 + p] = s;
        }
    } else if (bid < 544) {
        int idx = bid - 32;
        int bk = (idx & 7) * 32;
        int bn = (idx >> 3) * 32;
        int tx = tid & 31, ty = tid >> 5;
#pragma unroll
        for (int i = 0; i < 4; i++) {
            int k = bk + ty + i * 8;
            t[ty + i * 8][tx] = Wp[(size_t)k * ACOLS + bn + tx];
        }
        __syncthreads();
#pragma unroll
        for (int i = 0; i < 4; i++) {
            int n = bn + ty + i * 8;
            float v = t[tx][ty + i * 8];
            __nv_bfloat16 hh = __float2bfloat16(v);
            __nv_bfloat16 ll = __float2bfloat16(v - __bfloat162float(hh));
            g_WpTh[(size_t)n * DX + bk + tx] = hh;
            g_WpTl[(size_t)n * DX + bk + tx] = ll;
        }
    } else if (bid < 801) {
        __shared__ float red2[256];
        float* r = red2;
        int a = bid - 544;
        float s = 0.f;
        if (a < DX) {
            for (int j = tid; j < ACOLS; j += 256)
                s += Wp[(size_t)a * ACOLS + j] * bp[j];
        } else {
            for (int j = tid; j < ACOLS; j += 256) {
                float b = bp[j]; s += b * b;
            }
        }
        r[tid] = s;
        __syncthreads();
        for (int o = 128; o > 0; o >>= 1) {
            if (tid < o) r[tid] += r[tid + o];
            __syncthreads();
        }
        if (tid == 0) {
            if (a < DX) g_u[a] = r[0];
            else g_cb = r[0];
        }
    } else if (bid < 833) {
        int idx = bid - 801;
        int bk = (idx & 7) * 32;
        int bn = (idx >> 3) * 32;
        int tx = tid & 31, ty = tid >> 5;
#pragma unroll
        for (int i = 0; i < 4; i++) {
            int k = bk + ty + i * 8;
            t[ty + i * 8][tx] = Wf[(size_t)k * DOUT + bn + tx];
        }
        __syncthreads();
#pragma unroll
        for (int i = 0; i < 4; i++) {
            int n = bn + ty + i * 8;
            float v = t[tx][ty + i * 8];
            __nv_bfloat16 hh = __float2bfloat16(v);
            __nv_bfloat16 ll = __float2bfloat16(v - __bfloat162float(hh));
            g_WTh[(size_t)n * DX + bk + tx] = hh;
            g_WTl[(size_t)n * DX + bk + tx] = ll;
        }
    } else {
        int idx = bid - 833;  // 0..15
        for (int j = idx * 1024 + tid; j < (idx + 1) * 1024; j += 256)
            g_q[j] = 0.f;
        for (int j = idx * 4096 + tid; j < (idx + 1) * 4096; j += 256)
            g_M[j] = 0.f;
    }
}

// ---- M = Wp @ Wp^T via mma.sync, split-K (64 CTAs), fp32-direct load ----
__global__ void __launch_bounds__(256, 1) k_M_mma(const float* __restrict__ Wp) {
    __shared__ __nv_bfloat16 Ah[64 * 64], Al[64 * 64], Bh[64 * 64], Bl[64 * 64];
    uint32_t sAh = smem_to_u32(Ah), sAl = smem_to_u32(Al);
    uint32_t sBh = smem_to_u32(Bh), sBl = smem_to_u32(Bl);
    int tid = threadIdx.x, l = tid & 31, wid = tid >> 5;
    int a0 = blockIdx.x * 64, b0 = blockIdx.y * 64, k0 = blockIdx.z * 512;
    int warp_m = wid & 3, warp_n = wid >> 2;

    float acc[4][4];
#pragma unroll
    for (int a = 0; a < 4; a++)
#pragma unroll
        for (int c = 0; c < 4; c++) acc[a][c] = 0.f;

    int rA = warp_m * 16 + (l & 7) + ((l >> 3) & 1) * 8;
    int kA = (l >> 4) * 16;
    int rB = warp_n * 32 + (l & 7) + ((l >> 4) & 1) * 8;
    int kB = ((l >> 3) & 1) * 16;

    for (int kc = 0; kc < 8; kc++) {
        int kbase = k0 + kc * 64;
#pragma unroll
        for (int i = 0; i < 2; i++) {
            int idx = tid + i * 256;
            int row = idx >> 3;
            int colf = (idx & 7) * 8;
            uint32_t so = SMEM_SWIZZLE_128B((uint32_t)(row * 128 + colf * 2));
            const float* pa = Wp + (size_t)(a0 + row) * ACOLS + kbase + colf;
            const float* pb = Wp + (size_t)(b0 + row) * ACOLS + kbase + colf;
            float4 va0 = *(const float4*)pa;
            float4 va1 = *(const float4*)(pa + 4);
            float4 vb0 = *(const float4*)pb;
            float4 vb1 = *(const float4*)(pb + 4);
            __nv_bfloat16 hh[8], ll[8];
            float fa[8] = {va0.x, va0.y, va0.z, va0.w, va1.x, va1.y, va1.z, va1.w};
#pragma unroll
            for (int j = 0; j < 8; j++) {
                hh[j] = __float2bfloat16(fa[j]);
                ll[j] = __float2bfloat16(fa[j] - __bfloat162float(hh[j]));
            }
            *(uint4*)((char*)Ah + so) = *(uint4*)hh;
            *(uint4*)((char*)Al + so) = *(uint4*)ll;
            float fb[8] = {vb0.x, vb0.y, vb0.z, vb0.w, vb1.x, vb1.y, vb1.z, vb1.w};
#pragma unroll
            for (int j = 0; j < 8; j++) {
                hh[j] = __float2bfloat16(fb[j]);
                ll[j] = __float2bfloat16(fb[j] - __bfloat162float(hh[j]));
            }
            *(uint4*)((char*)Bh + so) = *(uint4*)hh;
            *(uint4*)((char*)Bl + so) = *(uint4*)ll;
        }
        __syncthreads();
#pragma unroll
        for (int ks = 0; ks < 4; ks++) {
            uint32_t aH[4], aL[4], bH[2][4], bL[2][4];
            {
                uint32_t off = SMEM_SWIZZLE_128B((uint32_t)(rA * 128 + ks * 32 + kA));
                ldsm4(aH, sAh + off);
                ldsm4(aL, sAl + off);
            }
#pragma unroll
            for (int ni = 0; ni < 2; ni++) {
                uint32_t off =
                    SMEM_SWIZZLE_128B((uint32_t)((rB + ni * 16) * 128 + ks * 32 + kB));
                ldsm4(bH[ni], sBh + off);
                ldsm4(bL[ni], sBl + off);
            }
#pragma unroll
            for (int nj = 0; nj < 4; nj++) {
                uint32_t* bh = &bH[nj >> 1][(nj & 1) * 2];
                uint32_t* bl = &bL[nj >> 1][(nj & 1) * 2];
                mma_bf16(acc[nj], aH, bh);
                mma_bf16(acc[nj], aL, bh);
                mma_bf16(acc[nj], aH, bl);
            }
        }
        __syncthreads();
    }
#pragma unroll
    for (int nj = 0; nj < 4; nj++) {
        int arow = a0 + warp_m * 16 + (l >> 2);
        int bcol = b0 + warp_n * 32 + nj * 8 + (l & 3) * 2;
        atomicAdd(&g_M[arow * DX + bcol], acc[nj][0]);
        atomicAdd(&g_M[arow * DX + bcol + 1], acc[nj][1]);
        atomicAdd(&g_M[(arow + 8) * DX + bcol], acc[nj][2]);
        atomicAdd(&g_M[(arow + 8) * DX + bcol + 1], acc[nj][3]);
    }
}

// ---------------- neighbor mean + bf16 split; tail blocks: M -> WT split ----
__device__ __forceinline__ void split_store(__nv_bfloat16* Hp, __nv_bfloat16* Lp,
                                            float4 v) {
    __nv_bfloat16 h[4], l[4];
    float f[4] = {v.x, v.y, v.z, v.w};
#pragma unroll
    for (int i = 0; i < 4; i++) {
        h[i] = __float2bfloat16(f[i]);
        l[i] = __float2bfloat16(f[i] - __bfloat162float(h[i]));
    }
    *(uint2*)Hp = *(uint2*)h;
    *(uint2*)Lp = *(uint2*)l;
}

__global__ void k_agg(const float* __restrict__ h) {
    if (blockIdx.x >= 2048) {
        // M symmetric: WT[128+r][c] = M[r][c], bf16 split. 64 blocks of 32x32.
        int idx = blockIdx.x - 2048;
        int br = (idx & 7) * 32;
        int bc = (idx >> 3) * 32;
        int tx = threadIdx.x & 31, ty = threadIdx.x >> 5;
#pragma unroll
        for (int i = 0; i < 4; i++) {
            int r = br + ty + i * 8;
            float v = g_M[r * DX + bc + tx];
            __nv_bfloat16 hh = __float2bfloat16(v);
            __nv_bfloat16 ll = __float2bfloat16(v - __bfloat162float(hh));
            g_WTh[(size_t)(128 + r) * DX + bc + tx] = hh;
            g_WTl[(size_t)(128 + r) * DX + bc + tx] = ll;
        }
        return;
    }
    int w = (blockIdx.x * blockDim.x + threadIdx.x) >> 5;
    int l = threadIdx.x & 31;
    int b = g_off[w], e = g_off[w + 1];
    float4 acc = make_float4(0.f, 0.f, 0.f, 0.f);
    int t = b;
    for (; t + 4 <= e; t += 4) {
        int s0 = g_csr[t], s1 = g_csr[t + 1], s2 = g_csr[t + 2], s3 = g_csr[t + 3];
        float4 v0 = *(const float4*)(h + (size_t)s0 * DIN + l * 4);
        float4 v1 = *(const float4*)(h + (size_t)s1 * DIN + l * 4);
        float4 v2 = *(const float4*)(h + (size_t)s2 * DIN + l * 4);
        float4 v3 = *(const float4*)(h + (size_t)s3 * DIN + l * 4);
        acc.x += (v0.x + v1.x) + (v2.x + v3.x);
        acc.y += (v0.y + v1.y) + (v2.y + v3.y);
        acc.z += (v0.z + v1.z) + (v2.z + v3.z);
        acc.w += (v0.w + v1.w) + (v2.w + v3.w);
    }
    for (; t < e; t++) {
        int s = g_csr[t];
        float4 v = *(const float4*)(h + (size_t)s * DIN + l * 4);
        acc.x += v.x; acc.y += v.y; acc.z += v.z; acc.w += v.w;
    }
    float inv = 1.f / fmaxf((float)(e - b), 1.f);
    float4 own = *(const float4*)(h + (size_t)w * DIN + l * 4);
    acc.x *= inv; acc.y *= inv; acc.z *= inv; acc.w *= inv;
    size_t base0 = (size_t)w * DX + l * 4;
    size_t base1 = base0 + DIN;
    split_store(g_Xh + base0, g_Xl + base0, own);
    split_store(g_Xh + base1, g_Xl + base1, acc);
}

// ---------------- main GEMM via mma.sync (bf16 split-2), cp.async dbuf ------
// R11 config: 128x128 tiles, grid (3,128), double-buffered cp.async.
#define KC 64
#define BUF_BYTES 65536
#define GA_H 0
#define GA_L 16384
#define GB_H 32768
#define GB_L 49152
#define SMEM_G (2 * BUF_BYTES)

__global__ void __launch_bounds__(256, 1) k_gemm_mma() {
    extern __shared__ char smem[];
    uint32_t sb = smem_to_u32(smem);
    int tid = threadIdx.x, l = tid & 31, wid = tid >> 5;
    int n0 = blockIdx.x * 128, m0 = blockIdx.y * 128;
    int warp_m = wid & 1, warp_n = wid >> 1;

    float acc[4][4][4];
#pragma unroll
    for (int a = 0; a < 4; a++)
#pragma unroll
        for (int b = 0; b < 4; b++)
#pragma unroll
            for (int c = 0; c < 4; c++) acc[a][b][c] = 0.f;

    int ldr[4], ldc[4];
#pragma unroll
    for (int i = 0; i < 4; i++) {
        int idx = tid + i * 256;
        ldr[i] = idx >> 3;
        ldc[i] = (idx & 7) * 16;
    }
    int rA = warp_m * 64 + (l & 7) + ((l >> 3) & 1) * 8;
    int kA = (l >> 4) * 16;
    int rB = warp_n * 32 + (l & 7) + ((l >> 4) & 1) * 8;
    int kB = ((l >> 3) & 1) * 16;

    {
#pragma unroll
        for (int i = 0; i < 4; i++) {
            int row = ldr[i];
            uint32_t so = SMEM_SWIZZLE_128B((uint32_t)(row * 128 + ldc[i]));
            size_t gA = (size_t)(m0 + row) * DX + (ldc[i] >> 1);
            size_t gB = (size_t)(n0 + row) * DX + (ldc[i] >> 1);
            cp16(sb + GA_H + so, g_Xh + gA);
            cp16(sb + GA_L + so, g_Xl + gA);
            cp16(sb + GB_H + so, g_WTh + gB);
            cp16(sb + GB_L + so, g_WTl + gB);
        }
        CP_COMMIT();
    }

    for (int c = 0; c < 4; c++) {
        uint32_t base = (uint32_t)(c & 1) * BUF_BYTES;
        if (c < 3) {
            uint32_t nb = (uint32_t)((c + 1) & 1) * BUF_BYTES;
            int koff = (c + 1) * KC;
#pragma unroll
            for (int i = 0; i < 4; i++) {
                int row = ldr[i];
                uint32_t so = SMEM_SWIZZLE_128B((uint32_t)(row * 128 + ldc[i]));
                size_t gA = (size_t)(m0 + row) * DX + koff + (ldc[i] >> 1);
                size_t gB = (size_t)(n0 + row) * DX + koff + (ldc[i] >> 1);
                cp16(sb + nb + GA_H + so, g_Xh + gA);
                cp16(sb + nb + GA_L + so, g_Xl + gA);
                cp16(sb + nb + GB_H + so, g_WTh + gB);
                cp16(sb + nb + GB_L + so, g_WTl + gB);
            }
            CP_COMMIT();
            CP_WAIT(1);
        } else {
            CP_WAIT(0);
        }
        __syncthreads();
#pragma unroll
        for (int ks = 0; ks < 4; ks++) {
            uint32_t aH[4][4], aL[4][4], bH[2][4], bL[2][4];
#pragma unroll
            for (int mi = 0; mi < 4; mi++) {
                uint32_t off =
                    SMEM_SWIZZLE_128B((uint32_t)((rA + mi * 16) * 128 + ks * 32 + kA));
                ldsm4(aH[mi], sb + base + GA_H + off);
                ldsm4(aL[mi], sb + base + GA_L + off);
            }
#pragma unroll
            for (int ni = 0; ni < 2; ni++) {
                uint32_t off =
                    SMEM_SWIZZLE_128B((uint32_t)((rB + ni * 16) * 128 + ks * 32 + kB));
                ldsm4(bH[ni], sb + base + GB_H + off);
                ldsm4(bL[ni], sb + base + GB_L + off);
            }
#pragma unroll
            for (int mi = 0; mi < 4; mi++)
#pragma unroll
                for (int nj = 0; nj < 4; nj++) {
                    uint32_t* bh = &bH[nj >> 1][(nj & 1) * 2];
                    uint32_t* bl = &bL[nj >> 1][(nj & 1) * 2];
                    mma_bf16(acc[mi][nj], aH[mi], bh);
                    mma_bf16(acc[mi][nj], aL[mi], bh);
                    mma_bf16(acc[mi][nj], aH[mi], bl);
                }
        }
        __syncthreads();
    }

    if (blockIdx.x == 0) {
#pragma unroll
        for (int mi = 0; mi < 4; mi++)
#pragma unroll
            for (int nj = 0; nj < 4; nj++) {
                int row = m0 + warp_m * 64 + mi * 16 + (l >> 2);
                int col = warp_n * 32 + nj * 8 + (l & 3) * 2;
                *(float2*)(g_C + (size_t)row * 128 + col) =
                    make_float2(acc[mi][nj][0], acc[mi][nj][1]);
                *(float2*)(g_C + (size_t)(row + 8) * 128 + col) =
                    make_float2(acc[mi][nj][2], acc[mi][nj][3]);
            }
    } else {
        float qr0[4] = {0.f, 0.f, 0.f, 0.f};
        float qr1[4] = {0.f, 0.f, 0.f, 0.f};
#pragma unroll
        for (int mi = 0; mi < 4; mi++) {
            int row = m0 + warp_m * 64 + mi * 16 + (l >> 2);
#pragma unroll
            for (int nj = 0; nj < 4; nj++) {
                int colX = (n0 - 128) + warp_n * 32 + nj * 8 + (l & 3) * 2;
                __nv_bfloat162 h01 = *(const __nv_bfloat162*)(g_Xh + (size_t)row * DX + colX);
                __nv_bfloat162 l01 = *(const __nv_bfloat162*)(g_Xl + (size_t)row * DX + colX);
                __nv_bfloat162 h23 = *(const __nv_bfloat162*)(g_Xh + (size_t)(row + 8) * DX + colX);
                __nv_bfloat162 l23 = *(const __nv_bfloat162*)(g_Xl + (size_t)(row + 8) * DX + colX);
                float2 hf01 = __bfloat1622float2(h01), lf01 = __bfloat1622float2(l01);
                float2 hf23 = __bfloat1622float2(h23), lf23 = __bfloat1622float2(l23);
                qr0[mi] += (hf01.x + lf01.x) * acc[mi][nj][0] +
                           (hf01.y + lf01.y) * acc[mi][nj][1];
                qr1[mi] += (hf23.x + lf23.x) * acc[mi][nj][2] +
                           (hf23.y + lf23.y) * acc[mi][nj][3];
            }
        }
#pragma unroll
        for (int mi = 0; mi < 4; mi++) {
            qr0[mi] += __shfl_xor_sync(0xffffffffu, qr0[mi], 1);
            qr0[mi] += __shfl_xor_sync(0xffffffffu, qr0[mi], 2);
            qr1[mi] += __shfl_xor_sync(0xffffffffu, qr1[mi], 1);
            qr1[mi] += __shfl_xor_sync(0xffffffffu, qr1[mi], 2);
        }
        if ((l & 3) == 0) {
#pragma unroll
            for (int mi = 0; mi < 4; mi++) {
                int row = m0 + warp_m * 64 + mi * 16 + (l >> 2);
                atomicAdd(&g_q[row], qr0[mi]);
                atomicAdd(&g_q[row + 8], qr1[mi]);
            }
        }
    }
}

// ---------------- post: feat normalize+relu, pool norm reciprocal ----------------
__global__ void k_post(const float* __restrict__ bfeat) {
    int w = (blockIdx.x * blockDim.x + threadIdx.x) >> 5;
    int l = threadIdx.x & 31;
    if (w >= NN) return;
    const __nv_bfloat16* Xh = g_Xh + (size_t)w * DX;
    const __nv_bfloat16* Xl = g_Xl + (size_t)w * DX;
    float xu = 0.f;
#pragma unroll
    for (int r = 0; r < 4; r++) {
        int j = (l + 32 * r) * 2;
        __nv_bfloat162 h2 = *(const __nv_bfloat162*)(Xh + j);
        __nv_bfloat162 l2 = *(const __nv_bfloat162*)(Xl + j);
        float2 hf = __bfloat1622float2(h2), lf = __bfloat1622float2(l2);
        xu += (hf.x + lf.x) * g_u[j] + (hf.y + lf.y) * g_u[j + 1];
    }
#pragma unroll
    for (int o = 16; o > 0; o >>= 1)
        xu += __shfl_xor_sync(0xffffffffu, xu, o);
    float n2 = g_q[w] + 2.f * xu + g_cb;
    float rn = 1.f / fmaxf(sqrtf(fmaxf(n2, 0.f)), 1e-12f);
    if (l == 0) g_rnp[w] = rn;

    const float* Crow = g_C + (size_t)w * 128;
    float f[4];
    float s2 = 0.f;
#pragma unroll
    for (int r = 0; r < 4; r++) {
        int j = l + 32 * r;
        f[r] = Crow[j] + bfeat[j];
        s2 += f[r] * f[r];
    }
#pragma unroll
    for (int o = 16; o > 0; o >>= 1) s2 += __shfl_xor_sync(0xffffffffu, s2, o);
    float rf = 1.f / fmaxf(sqrtf(s2), 1e-12f);
#pragma unroll
    for (int r = 0; r < 4; r++)
        g_feat[(size_t)w * DOUT + l + 32 * r] = fmaxf(f[r] * rf, 0.f);
}

// ---------------- assign GEMM via mma.sync + fused softmax ----------------
#define AA_H 0
#define AA_L 16384
#define AB_H 32768
#define AB_L 40960
#define SMEM_A 49152

__global__ void __launch_bounds__(256, 2) k_assign_mma(const float* __restrict__ bp) {
    extern __shared__ char smem[];
    uint32_t sb = smem_to_u32(smem);
    int tid = threadIdx.x, l = tid & 31, wid = tid >> 5;
    int g = blockIdx.y;
    int n0g = g * NPER + blockIdx.x * 128;
    int warp_m = wid & 1, warp_n = wid >> 1;

    float acc[4][2][4];
#pragma unroll
    for (int a = 0; a < 4; a++)
#pragma unroll
        for (int b = 0; b < 2; b++)
#pragma unroll
            for (int c = 0; c < 4; c++) acc[a][b][c] = 0.f;

    int rA = warp_m * 64 + (l & 7) + ((l >> 3) & 1) * 8;
    int kA = (l >> 4) * 16;
    int rB = warp_n * 16 + (l & 7) + ((l >> 4) & 1) * 8;
    int kB = ((l >> 3) & 1) * 16;

    for (int c = 0; c < 4; c++) {
#pragma unroll
        for (int i = 0; i < 4; i++) {
            int idx = tid + i * 256;
            int row = idx >> 3, cb = (idx & 7) * 16;
            uint32_t so = SMEM_SWIZZLE_128B((uint32_t)(row * 128 + cb));
            size_t gA = (size_t)(n0g + row) * DX + c * KC + (cb >> 1);
            *(uint4*)(smem + AA_H + so) = *(const uint4*)(g_Xh + gA);
            *(uint4*)(smem + AA_L + so) = *(const uint4*)(g_Xl + gA);
        }
#pragma unroll
        for (int i = 0; i < 2; i++) {
            int idx = tid + i * 256;
            int row = idx >> 3, cb = (idx & 7) * 16;
            uint32_t so = SMEM_SWIZZLE_128B((uint32_t)(row * 128 + cb));
            size_t gB = (size_t)(g * KCL + row) * DX + c * KC + (cb >> 1);
            *(uint4*)(smem + AB_H + so) = *(const uint4*)(g_WpTh + gB);
            *(uint4*)(smem + AB_L + so) = *(const uint4*)(g_WpTl + gB);
        }
        __syncthreads();
#pragma unroll
        for (int ks = 0; ks < 4; ks++) {
            uint32_t aH[4][4], aL[4][4], bH[4], bL[4];
#pragma unroll
            for (int mi = 0; mi < 4; mi++) {
                uint32_t off =
                    SMEM_SWIZZLE_128B((uint32_t)((rA + mi * 16) * 128 + ks * 32 + kA));
                ldsm4(aH[mi], sb + AA_H + off);
                ldsm4(aL[mi], sb + AA_L + off);
            }
            {
                uint32_t off =
                    SMEM_SWIZZLE_128B((uint32_t)(rB * 128 + ks * 32 + kB));
                ldsm4(bH, sb + AB_H + off);
                ldsm4(bL, sb + AB_L + off);
            }
#pragma unroll
            for (int mi = 0; mi < 4; mi++)
#pragma unroll
                for (int nj = 0; nj < 2; nj++) {
                    const uint32_t* bh = &bH[nj * 2];
                    const uint32_t* bl = &bL[nj * 2];
                    mma_bf16(acc[mi][nj], aH[mi], bh);
                    mma_bf16(acc[mi][nj], aL[mi], bh);
                    mma_bf16(acc[mi][nj], aH[mi], bl);
                }
        }
        __syncthreads();
    }
    float(*Zs)[66] = (float(*)[66])smem;
#pragma unroll
    for (int mi = 0; mi < 4; mi++)
#pragma unroll
        for (int nj = 0; nj < 2; nj++) {
            int row = warp_m * 64 + mi * 16 + (l >> 2);
            int col = warp_n * 16 + nj * 8 + (l & 3) * 2;
            *(float2*)(&Zs[row][col]) = make_float2(acc[mi][nj][0], acc[mi][nj][1]);
            *(float2*)(&Zs[row + 8][col]) = make_float2(acc[mi][nj][2], acc[mi][nj][3]);
        }
    __syncthreads();

    for (int rr = 0; rr < 16; rr++) {
        int row = wid * 16 + rr;
        int node = n0g + row;
        float rn = g_rnp[node];
        float v0 = fmaxf((Zs[row][l] + bp[g * KCL + l]) * rn, 0.f);
        float v1 = fmaxf((Zs[row][l + 32] + bp[g * KCL + l + 32]) * rn, 0.f);
        float e0 = expf(v0), e1 = expf(v1);
        float t = e0 + e1;
#pragma unroll
        for (int o = 16; o > 0; o >>= 1) t += __shfl_xor_sync(0xffffffffu, t, o);
        float inv = 1.f / t;
        g_s[(size_t)node * KCL + l] = e0 * inv;
        g_s[(size_t)node * KCL + l + 32] = e1 * inv;
    }
}

// ---------------- fused pooling: gather a_s + h_new + adj blocks ----------------
#define SMEM_P 65536
__global__ void __launch_bounds__(256, 1) k_pool(float* __restrict__ out) {
    extern __shared__ char smemc[];
    float* Ss = (float*)smemc;            // [64][64]
    float* Ff = Ss + 64 * 64;             // [64][128]
    float* Aa = Ff + 64 * 128;            // [64][64]
    int g = blockIdx.y;
    int n0 = g * NPER + blockIdx.x * 64;
    int tid = threadIdx.x;
    int wid = tid >> 5, l = tid & 31;

#pragma unroll
    for (int q = 0; q < 16; q++) {
        int idx = tid + q * 256;
        Ss[idx] = g_s[(size_t)n0 * KCL + idx];
    }
#pragma unroll
    for (int q = 0; q < 32; q++) {
        int idx = tid + q * 256;
        Ff[idx] = g_feat[(size_t)n0 * DOUT + idx];
    }

    for (int r = 0; r < 8; r++) {
        int row = wid * 8 + r;
        int node = n0 + row;
        int b = g_off[node], e = g_off[node + 1];
        float a0 = 0.f, a1 = 0.f;
        int t = b;
        for (; t + 4 <= e; t += 4) {
            int s0 = g_csr[t], s1 = g_csr[t + 1], s2 = g_csr[t + 2], s3 = g_csr[t + 3];
            float p0 = g_s[(size_t)s0 * KCL + l], q0 = g_s[(size_t)s0 * KCL + 32 + l];
            float p1 = g_s[(size_t)s1 * KCL + l], q1 = g_s[(size_t)s1 * KCL + 32 + l];
            float p2 = g_s[(size_t)s2 * KCL + l], q2 = g_s[(size_t)s2 * KCL + 32 + l];
            float p3 = g_s[(size_t)s3 * KCL + l], q3 = g_s[(size_t)s3 * KCL + 32 + l];
            a0 += (p0 + p1) + (p2 + p3);
            a1 += (q0 + q1) + (q2 + q3);
        }
        for (; t < e; t++) {
            int s = g_csr[t];
            a0 += g_s[(size_t)s * KCL + l];
            a1 += g_s[(size_t)s * KCL + 32 + l];
        }
        Aa[row * 64 + l] = a0;
        Aa[row * 64 + 32 + l] = a1;
    }
    __syncthreads();

    {
        int tx = tid & 31, ty = tid >> 5;
        unsigned long long acc[8][2];
#pragma unroll
        for (int r = 0; r < 8; r++) { acc[r][0] = 0ull; acc[r][1] = 0ull; }
        for (int k = 0; k < 64; k++) {
            float4 f4 = *(float4*)(&Ff[k * 128 + tx * 4]);
            unsigned long long fp0 = pk2(f4.x, f4.y);
            unsigned long long fp1 = pk2(f4.z, f4.w);
#pragma unroll
            for (int r = 0; r < 8; r++) {
                float a = Ss[k * 64 + ty * 8 + r];
                unsigned long long ab = pk2(a, a);
                fma2(acc[r][0], ab, fp0);
                fma2(acc[r][1], ab, fp1);
            }
        }
#pragma unroll
        for (int r = 0; r < 8; r++) {
            float2 u0 = up2(acc[r][0]), u1 = up2(acc[r][1]);
            float v[4] = {u0.x, u0.y, u1.x, u1.y};
            size_t base = (size_t)ADJ_OFF + (size_t)(g * KCL + ty * 8 + r) * DOUT + tx * 4;
#pragma unroll
            for (int j = 0; j < 4; j++) atomicAdd(out + base + j, v[j]);
        }
    }

    {
        int tx = tid & 15, ty = tid >> 4;
        unsigned long long acc[2][4];
#pragma unroll
        for (int p = 0; p < 2; p++)
#pragma unroll
            for (int j = 0; j < 4; j++) acc[p][j] = 0ull;
        for (int k = 0; k < 64; k++) {
            float4 a4 = *(float4*)(&Ss[k * 64 + ty * 4]);
            unsigned long long ap0 = pk2(a4.x, a4.y);
            unsigned long long ap1 = pk2(a4.z, a4.w);
            float4 b4 = *(float4*)(&Aa[k * 64 + tx * 4]);
            float bsc[4] = {b4.x, b4.y, b4.z, b4.w};
#pragma unroll
            for (int j = 0; j < 4; j++) {
                unsigned long long bb = pk2(bsc[j], bsc[j]);
                fma2(acc[0][j], ap0, bb);
                fma2(acc[1][j], ap1, bb);
            }
        }
#pragma unroll
        for (int p = 0; p < 2; p++)
#pragma unroll
            for (int c = 0; c < 2; c++) {
                int row = g * KCL + ty * 4 + 2 * p + c;
                size_t base = (size_t)row * 2048 + g * KCL + tx * 4;
#pragma unroll
                for (int j = 0; j < 4; j++) {
                    float2 u = up2(acc[p][j]);
                    atomicAdd(out + base + j, c == 0 ? u.x : u.y);
                }
            }
    }
}

// ---------------- launch ----------------
extern "C" void kernel_launch(void* const* d_in, const int* in_sizes, int n_in,
                              void* d_out, int out_size) {
    const float* h  = (const float*)d_in[0];
    const float* Wf = (const float*)d_in[1];
    const float* bf = (const float*)d_in[2];
    const float* Wp = (const float*)d_in[3];
    const float* bp = (const float*)d_in[4];
    const int* esrc = (const int*)d_in[5];
    const int* edst = (const int*)d_in[6];
    int E = in_sizes[5];
    float* out = (float*)d_out;

    cudaFuncSetAttribute(k_gemm_mma, cudaFuncAttributeMaxDynamicSharedMemorySize,
                         SMEM_G);
    cudaFuncSetAttribute(k_assign_mma, cudaFuncAttributeMaxDynamicSharedMemorySize,
                         SMEM_A);
    cudaFuncSetAttribute(k_pool, cudaFuncAttributeMaxDynamicSharedMemorySize,
                         SMEM_P);

    cudaMemsetAsync(d_out, 0, (size_t)out_size * sizeof(float));
    k_setup<<<849, 256>>>(Wf, Wp, bp, esrc, edst, E);
    k_M_mma<<<dim3(4, 4, 4), 256>>>(Wp);
    k_agg<<<2048 + 64, 256>>>(h);
    k_gemm_mma<<<dim3(3, 128), 256, SMEM_G>>>();
    k_post<<<2048, 256>>>(bf);
    k_assign_mma<<<dim3(4, BG), 256, SMEM_A>>>(bp);
    k_pool<<<dim3(8, BG), 256, SMEM_P>>>(out);
}